// round 2
// baseline (speedup 1.0000x reference)
#include <cuda_runtime.h>
#include <cuda_bf16.h>

// CoLAttention, restructured:
//   M[d][a]  = (1/32) * sum_e W_Q[e][d] * C_K[e][a]      (prep kernel, 134 MFLOP)
//   bias[a]  = (1/32) * sum_e b_Q[e]    * C_K[e][a]
//   logits[r][a] = sum_d x[r][d]*M[d][a] + bias[a]
//   A = softmax(logits) * mask
//   out[r][d] = sum_a A[r][a] * C_V[d][a]

#define DIM    1024
#define ALPHA  64
#define NROWS  32768           // B*L = 8*4096
#define SCALE  0.03125f        // 1/sqrt(1024)

__device__ float g_M[DIM * ALPHA];
__device__ float g_bias[ALPHA];

// ---------------------------------------------------------------------------
// Prep: M = (W_Q^T @ C_K) / 32.  256 blocks, each owns 4 d-columns x 64 a.
// ---------------------------------------------------------------------------
__global__ __launch_bounds__(256) void prep_M_kernel(
    const float* __restrict__ W_Q, const float* __restrict__ C_K)
{
    __shared__ float ck_s[128][ALPHA];   // 32 KB
    __shared__ float wq_s[128][4];       //  2 KB
    const int tid = threadIdx.x;
    const int d0  = blockIdx.x * 4;
    const int a   = tid & 63;
    const int dl  = tid >> 6;

    float acc = 0.f;
    for (int e0 = 0; e0 < DIM; e0 += 128) {
        #pragma unroll
        for (int i = tid; i < 128 * ALPHA; i += 256)
            ck_s[i >> 6][i & 63] = C_K[(e0 + (i >> 6)) * ALPHA + (i & 63)];
        #pragma unroll
        for (int i = tid; i < 128 * 4; i += 256)
            wq_s[i >> 2][i & 3] = W_Q[(e0 + (i >> 2)) * DIM + d0 + (i & 3)];
        __syncthreads();
        #pragma unroll 16
        for (int e = 0; e < 128; e++)
            acc += wq_s[e][dl] * ck_s[e][a];
        __syncthreads();
    }
    g_M[(d0 + dl) * ALPHA + a] = acc * SCALE;
}

// ---------------------------------------------------------------------------
// Prep: bias = (b_Q @ C_K) / 32.  One block, 64 threads.
// ---------------------------------------------------------------------------
__global__ void prep_bias_kernel(
    const float* __restrict__ b_Q, const float* __restrict__ C_K)
{
    const int a = threadIdx.x;
    float acc = 0.f;
    #pragma unroll 8
    for (int e = 0; e < DIM; e++)
        acc += b_Q[e] * C_K[e * ALPHA + a];
    g_bias[a] = acc * SCALE;
}

// ---------------------------------------------------------------------------
// Fused main: one block = 64 rows. 256 threads, thread tile 4x4.
//   phase 1: logits(64x64) = X(64x1024) @ M(1024x64)      [k-tiled 32]
//   phase 2: row softmax * mask
//   phase 3: out(64x1024)  = A(64x64)  @ C_V^T            [d-tiled 64]
// ---------------------------------------------------------------------------
#define ROWS 64

__global__ __launch_bounds__(256, 2) void fused_kernel(
    const float* __restrict__ x, const int* __restrict__ mask,
    const float* __restrict__ C_V, float* __restrict__ out)
{
    // phase-1 tiles and the phase-3 C_V tile share storage (disjoint lifetimes)
    __shared__ __align__(16) float sbuf[64 * 65];   // >= max(32*65 + 32*64, 64*65)
    __shared__ float ls[64][65];                    // logits, then A

    float (*xs)[65] = (float (*)[65])sbuf;          // xs[k][r], 32*65
    float (*ms)[64] = (float (*)[64])(sbuf + 32 * 65 + 12); // ms[k][a], 32*64 (offset kept 16B aligned)
    float (*cs)[65] = (float (*)[65])sbuf;          // cs[dl][a], 64*65 (phase 3)

    const int tid = threadIdx.x;
    const int tx  = tid & 15;           // a/d tile coordinate
    const int ty  = tid >> 4;           // row tile coordinate
    const int row0 = blockIdx.x * ROWS;

    // ---- phase 1: logits ----
    float acc[4][4];
    {
        const float4 b4 = *(const float4*)&g_bias[tx * 4];
        #pragma unroll
        for (int j = 0; j < 4; j++) {
            acc[j][0] = b4.x; acc[j][1] = b4.y; acc[j][2] = b4.z; acc[j][3] = b4.w;
        }
    }

    for (int k0 = 0; k0 < DIM; k0 += 32) {
        // load X tile 64 rows x 32 k  -> xs[k][r]
        #pragma unroll
        for (int s = 0; s < 2; s++) {
            const int v  = tid + 256 * s;
            const int r  = v >> 3;
            const int kq = v & 7;
            const float4 t4 = *(const float4*)&x[(row0 + r) * DIM + k0 + kq * 4];
            xs[kq * 4 + 0][r] = t4.x;
            xs[kq * 4 + 1][r] = t4.y;
            xs[kq * 4 + 2][r] = t4.z;
            xs[kq * 4 + 3][r] = t4.w;
        }
        // load M tile 32 k x 64 a -> ms[k][a]
        #pragma unroll
        for (int s = 0; s < 2; s++) {
            const int v  = tid + 256 * s;
            const int k  = v >> 4;
            const int aq = v & 15;
            *(float4*)&ms[k][aq * 4] = *(const float4*)&g_M[(k0 + k) * ALPHA + aq * 4];
        }
        __syncthreads();

        #pragma unroll 8
        for (int k = 0; k < 32; k++) {
            const float4 m4 = *(const float4*)&ms[k][tx * 4];
            #pragma unroll
            for (int j = 0; j < 4; j++) {
                const float xv = xs[k][ty * 4 + j];
                acc[j][0] += xv * m4.x;
                acc[j][1] += xv * m4.y;
                acc[j][2] += xv * m4.z;
                acc[j][3] += xv * m4.w;
            }
        }
        __syncthreads();
    }

    // stash logits
    #pragma unroll
    for (int j = 0; j < 4; j++) {
        ls[ty * 4 + j][tx * 4 + 0] = acc[j][0];
        ls[ty * 4 + j][tx * 4 + 1] = acc[j][1];
        ls[ty * 4 + j][tx * 4 + 2] = acc[j][2];
        ls[ty * 4 + j][tx * 4 + 3] = acc[j][3];
    }
    __syncthreads();

    // ---- phase 2: softmax * mask (one thread per row) ----
    if (tid < ROWS) {
        float mx = ls[tid][0];
        #pragma unroll 16
        for (int a = 1; a < ALPHA; a++) mx = fmaxf(mx, ls[tid][a]);
        float sum = 0.f;
        #pragma unroll 16
        for (int a = 0; a < ALPHA; a++) {
            const float e = __expf(ls[tid][a] - mx);
            sum += e;
            ls[tid][a] = e;
        }
        const float mv  = mask[row0 + tid] ? 1.0f : 0.0f;   // mask stored as int32
        const float inv = mv / sum;
        #pragma unroll 16
        for (int a = 0; a < ALPHA; a++) ls[tid][a] *= inv;
    }
    __syncthreads();

    // ---- phase 3: out = A @ C_V^T ----
    for (int d0 = 0; d0 < DIM; d0 += 64) {
        #pragma unroll
        for (int s = 0; s < 4; s++) {
            const int v  = tid + 256 * s;
            const int dl = v >> 4;
            const int aq = v & 15;
            const float4 c4 = *(const float4*)&C_V[(d0 + dl) * ALPHA + aq * 4];
            cs[dl][aq * 4 + 0] = c4.x;
            cs[dl][aq * 4 + 1] = c4.y;
            cs[dl][aq * 4 + 2] = c4.z;
            cs[dl][aq * 4 + 3] = c4.w;
        }
        __syncthreads();

        float o[4][4] = {};
        #pragma unroll 8
        for (int a = 0; a < ALPHA; a++) {
            float lv[4], cv[4];
            #pragma unroll
            for (int j = 0; j < 4; j++) lv[j] = ls[ty * 4 + j][a];
            #pragma unroll
            for (int i = 0; i < 4; i++) cv[i] = cs[tx * 4 + i][a];
            #pragma unroll
            for (int j = 0; j < 4; j++)
                #pragma unroll
                for (int i = 0; i < 4; i++)
                    o[j][i] += lv[j] * cv[i];
        }

        #pragma unroll
        for (int j = 0; j < 4; j++) {
            float4 w;
            w.x = o[j][0]; w.y = o[j][1]; w.z = o[j][2]; w.w = o[j][3];
            *(float4*)&out[(row0 + ty * 4 + j) * DIM + d0 + tx * 4] = w;
        }
        __syncthreads();
    }
}

// ---------------------------------------------------------------------------
extern "C" void kernel_launch(void* const* d_in, const int* in_sizes, int n_in,
                              void* d_out, int out_size)
{
    const float* x    = (const float*)d_in[0];
    const int*   mask = (const int*)d_in[1];
    const float* W_Q  = (const float*)d_in[2];
    const float* b_Q  = (const float*)d_in[3];
    const float* C_K  = (const float*)d_in[4];
    const float* C_V  = (const float*)d_in[5];
    float*       out  = (float*)d_out;

    prep_M_kernel<<<DIM / 4, 256>>>(W_Q, C_K);
    prep_bias_kernel<<<1, ALPHA>>>(b_Q, C_K);
    fused_kernel<<<NROWS / ROWS, 256>>>(x, mask, C_V, out);
}

// round 3
// speedup vs baseline: 1.0055x; 1.0055x over previous
#include <cuda_runtime.h>
#include <cuda_bf16.h>

// CoLAttention, restructured:
//   M[d][a]  = (1/32) * sum_e W_Q[e][d] * C_K[e][a]      (prep kernel, 134 MFLOP)
//   bias[a]  = (1/32) * sum_e b_Q[e]    * C_K[e][a]
//   logits[r][a] = sum_d x[r][d]*M[d][a] + bias[a]
//   A = softmax(logits) * mask
//   out[r][d] = sum_a A[r][a] * C_V[d][a]

#define DIM    1024
#define ALPHA  64
#define NROWS  32768           // B*L = 8*4096
#define SCALE  0.03125f        // 1/sqrt(1024)

__device__ float g_M[DIM * ALPHA];
__device__ float g_bias[ALPHA];

// ---------------------------------------------------------------------------
// Prep: M = (W_Q^T @ C_K) / 32.  256 blocks, each owns 4 d-columns x 64 a.
// ---------------------------------------------------------------------------
__global__ __launch_bounds__(256) void prep_M_kernel(
    const float* __restrict__ W_Q, const float* __restrict__ C_K)
{
    __shared__ float ck_s[128][ALPHA];   // 32 KB
    __shared__ float wq_s[128][4];       //  2 KB
    const int tid = threadIdx.x;
    const int d0  = blockIdx.x * 4;
    const int a   = tid & 63;
    const int dl  = tid >> 6;

    float acc = 0.f;
    for (int e0 = 0; e0 < DIM; e0 += 128) {
        #pragma unroll
        for (int i = tid; i < 128 * ALPHA; i += 256)
            ck_s[i >> 6][i & 63] = C_K[(e0 + (i >> 6)) * ALPHA + (i & 63)];
        #pragma unroll
        for (int i = tid; i < 128 * 4; i += 256)
            wq_s[i >> 2][i & 3] = W_Q[(e0 + (i >> 2)) * DIM + d0 + (i & 3)];
        __syncthreads();
        #pragma unroll 16
        for (int e = 0; e < 128; e++)
            acc += wq_s[e][dl] * ck_s[e][a];
        __syncthreads();
    }
    g_M[(d0 + dl) * ALPHA + a] = acc * SCALE;
}

// ---------------------------------------------------------------------------
// Prep: bias = (b_Q @ C_K) / 32.  One block, 64 threads.
// ---------------------------------------------------------------------------
__global__ void prep_bias_kernel(
    const float* __restrict__ b_Q, const float* __restrict__ C_K)
{
    const int a = threadIdx.x;
    float acc = 0.f;
    #pragma unroll 8
    for (int e = 0; e < DIM; e++)
        acc += b_Q[e] * C_K[e * ALPHA + a];
    g_bias[a] = acc * SCALE;
}

// ---------------------------------------------------------------------------
// Fused main: one block = 64 rows. 256 threads, thread tile 4x4.
//   phase 1: logits(64x64) = X(64x1024) @ M(1024x64)      [k-tiled 32]
//   phase 2: row softmax * mask
//   phase 3: out(64x1024)  = A(64x64)  @ C_V^T            [d-tiled 64]
// ---------------------------------------------------------------------------
#define ROWS 64

__global__ __launch_bounds__(256, 2) void fused_kernel(
    const float* __restrict__ x, const int* __restrict__ mask,
    const float* __restrict__ C_V, float* __restrict__ out)
{
    // phase-1 tiles and the phase-3 C_V tile share storage (disjoint lifetimes)
    __shared__ __align__(16) float sbuf[64 * 65];   // >= max(32*65 + 32*64, 64*65)
    __shared__ float ls[64][65];                    // logits, then A

    float (*xs)[65] = (float (*)[65])sbuf;          // xs[k][r], 32*65
    float (*ms)[64] = (float (*)[64])(sbuf + 32 * 65 + 12); // ms[k][a], 32*64 (offset kept 16B aligned)
    float (*cs)[65] = (float (*)[65])sbuf;          // cs[dl][a], 64*65 (phase 3)

    const int tid = threadIdx.x;
    const int tx  = tid & 15;           // a/d tile coordinate
    const int ty  = tid >> 4;           // row tile coordinate
    const int row0 = blockIdx.x * ROWS;

    // ---- phase 1: logits ----
    float acc[4][4];
    {
        const float4 b4 = *(const float4*)&g_bias[tx * 4];
        #pragma unroll
        for (int j = 0; j < 4; j++) {
            acc[j][0] = b4.x; acc[j][1] = b4.y; acc[j][2] = b4.z; acc[j][3] = b4.w;
        }
    }

    for (int k0 = 0; k0 < DIM; k0 += 32) {
        // load X tile 64 rows x 32 k  -> xs[k][r]
        #pragma unroll
        for (int s = 0; s < 2; s++) {
            const int v  = tid + 256 * s;
            const int r  = v >> 3;
            const int kq = v & 7;
            const float4 t4 = *(const float4*)&x[(row0 + r) * DIM + k0 + kq * 4];
            xs[kq * 4 + 0][r] = t4.x;
            xs[kq * 4 + 1][r] = t4.y;
            xs[kq * 4 + 2][r] = t4.z;
            xs[kq * 4 + 3][r] = t4.w;
        }
        // load M tile 32 k x 64 a -> ms[k][a]
        #pragma unroll
        for (int s = 0; s < 2; s++) {
            const int v  = tid + 256 * s;
            const int k  = v >> 4;
            const int aq = v & 15;
            *(float4*)&ms[k][aq * 4] = *(const float4*)&g_M[(k0 + k) * ALPHA + aq * 4];
        }
        __syncthreads();

        #pragma unroll 8
        for (int k = 0; k < 32; k++) {
            const float4 m4 = *(const float4*)&ms[k][tx * 4];
            #pragma unroll
            for (int j = 0; j < 4; j++) {
                const float xv = xs[k][ty * 4 + j];
                acc[j][0] += xv * m4.x;
                acc[j][1] += xv * m4.y;
                acc[j][2] += xv * m4.z;
                acc[j][3] += xv * m4.w;
            }
        }
        __syncthreads();
    }

    // stash logits
    #pragma unroll
    for (int j = 0; j < 4; j++) {
        ls[ty * 4 + j][tx * 4 + 0] = acc[j][0];
        ls[ty * 4 + j][tx * 4 + 1] = acc[j][1];
        ls[ty * 4 + j][tx * 4 + 2] = acc[j][2];
        ls[ty * 4 + j][tx * 4 + 3] = acc[j][3];
    }
    __syncthreads();

    // ---- phase 2: softmax * mask (one thread per row) ----
    if (tid < ROWS) {
        float mx = ls[tid][0];
        #pragma unroll 16
        for (int a = 1; a < ALPHA; a++) mx = fmaxf(mx, ls[tid][a]);
        float sum = 0.f;
        #pragma unroll 16
        for (int a = 0; a < ALPHA; a++) {
            const float e = __expf(ls[tid][a] - mx);
            sum += e;
            ls[tid][a] = e;
        }
        const float mv  = mask[row0 + tid] ? 1.0f : 0.0f;   // mask stored as int32
        const float inv = mv / sum;
        #pragma unroll 16
        for (int a = 0; a < ALPHA; a++) ls[tid][a] *= inv;
    }
    __syncthreads();

    // ---- phase 3: out = A @ C_V^T ----
    for (int d0 = 0; d0 < DIM; d0 += 64) {
        #pragma unroll
        for (int s = 0; s < 4; s++) {
            const int v  = tid + 256 * s;
            const int dl = v >> 4;
            const int aq = v & 15;
            const float4 c4 = *(const float4*)&C_V[(d0 + dl) * ALPHA + aq * 4];
            cs[dl][aq * 4 + 0] = c4.x;
            cs[dl][aq * 4 + 1] = c4.y;
            cs[dl][aq * 4 + 2] = c4.z;
            cs[dl][aq * 4 + 3] = c4.w;
        }
        __syncthreads();

        float o[4][4] = {};
        #pragma unroll 8
        for (int a = 0; a < ALPHA; a++) {
            float lv[4], cv[4];
            #pragma unroll
            for (int j = 0; j < 4; j++) lv[j] = ls[ty * 4 + j][a];
            #pragma unroll
            for (int i = 0; i < 4; i++) cv[i] = cs[tx * 4 + i][a];
            #pragma unroll
            for (int j = 0; j < 4; j++)
                #pragma unroll
                for (int i = 0; i < 4; i++)
                    o[j][i] += lv[j] * cv[i];
        }

        #pragma unroll
        for (int j = 0; j < 4; j++) {
            float4 w;
            w.x = o[j][0]; w.y = o[j][1]; w.z = o[j][2]; w.w = o[j][3];
            *(float4*)&out[(row0 + ty * 4 + j) * DIM + d0 + tx * 4] = w;
        }
        __syncthreads();
    }
}

// ---------------------------------------------------------------------------
extern "C" void kernel_launch(void* const* d_in, const int* in_sizes, int n_in,
                              void* d_out, int out_size)
{
    const float* x    = (const float*)d_in[0];
    const int*   mask = (const int*)d_in[1];
    const float* W_Q  = (const float*)d_in[2];
    const float* b_Q  = (const float*)d_in[3];
    const float* C_K  = (const float*)d_in[4];
    const float* C_V  = (const float*)d_in[5];
    float*       out  = (float*)d_out;

    prep_M_kernel<<<DIM / 4, 256>>>(W_Q, C_K);
    prep_bias_kernel<<<1, ALPHA>>>(b_Q, C_K);
    fused_kernel<<<NROWS / ROWS, 256>>>(x, mask, C_V, out);
}

// round 5
// speedup vs baseline: 2.2687x; 2.2563x over previous
#include <cuda_runtime.h>
#include <cuda_fp16.h>
#include <cstdint>
#include <cstddef>

#define DIM    1024
#define ALPHA  64
#define NROWS  32768
#define SCALE  0.03125f        // 1/sqrt(1024)
#define TILE_ROWS 128
#define NCTA   (NROWS / TILE_ROWS)

// operand pre-scales (powers of 2, folded out exactly)
#define MT_S   256.0f
#define INV_MT (1.0f / 256.0f)
#define A_S    1024.0f
#define CV_S   64.0f
#define OUT_S  (1.0f / (1024.0f * 64.0f))

// smem layout (bytes). Aliasing by lifetime:
//   phase1: xs[128][72]h @0 (18432), mts[64][72]h @18432 (9216)
//   phase2: ls[128][68]f @0 (34816)  [xs/mts dead]
//   A:      ah[128][72]h @36864, al @55296 (alive through phase 3)
//   phase3: cvh[128][72]h @0, cvl @18432   [ls dead]
#define XS_OFF   0
#define MTS_OFF  18432
#define LS_OFF   0
#define AH_OFF   36864
#define AL_OFF   55296
#define CVH_OFF  0
#define CVL_OFF  18432
#define BIAS_OFF 73728
#define SMEM_BYTES 73984

__device__ float  g_part[16 * ALPHA * DIM];     // K-split partials for Mt
__device__ float  g_bias[ALPHA];
__device__ __half g_Mth[ALPHA * DIM];           // Mt[a][d] * 256, fp16
__device__ __half g_CVh[DIM * ALPHA];           // C_V[d][a]*64 hi
__device__ __half g_CVl[DIM * ALPHA];           // residual lo

// ---------------- helpers ----------------
__device__ __forceinline__ uint32_t fpack(float a, float b) {
    __half2 h = __floats2half2_rn(a, b);
    return *reinterpret_cast<uint32_t*>(&h);
}
__device__ __forceinline__ void mma16816(float* c, const uint32_t* a, const uint32_t* b) {
    asm volatile("mma.sync.aligned.m16n8k16.row.col.f32.f16.f16.f32 "
        "{%0,%1,%2,%3}, {%4,%5,%6,%7}, {%8,%9}, {%0,%1,%2,%3};"
        : "+f"(c[0]), "+f"(c[1]), "+f"(c[2]), "+f"(c[3])
        : "r"(a[0]), "r"(a[1]), "r"(a[2]), "r"(a[3]), "r"(b[0]), "r"(b[1]));
}

// ---------------- prep: partial GEMM  Mt_part = C_K^T @ W_Q (K-split 16x64) ----------------
__global__ __launch_bounds__(256) void prep_partial(
    const float* __restrict__ W_Q, const float* __restrict__ C_K)
{
    __shared__ float ck_s[64][68];
    __shared__ float wq_s[64][68];
    const int tid = threadIdx.x;
    const int nb = blockIdx.x & 15, kb = blockIdx.x >> 4;
    const int e0 = kb * 64, d0 = nb * 64;
    #pragma unroll
    for (int j = 0; j < 4; j++) {
        const int v = tid + 256 * j;
        const int e = v >> 4, q = v & 15;
        *(float4*)&ck_s[e][q * 4] = *(const float4*)&C_K[(e0 + e) * ALPHA + q * 4];
        *(float4*)&wq_s[e][q * 4] = *(const float4*)&W_Q[(size_t)(e0 + e) * DIM + d0 + q * 4];
    }
    __syncthreads();
    const int tx = tid & 15, ty = tid >> 4;
    float acc[4][4] = {};
    #pragma unroll 8
    for (int e = 0; e < 64; e++) {
        const float4 av = *(const float4*)&ck_s[e][ty * 4];
        const float4 bv = *(const float4*)&wq_s[e][tx * 4];
        const float aa[4] = {av.x, av.y, av.z, av.w};
        const float bb[4] = {bv.x, bv.y, bv.z, bv.w};
        #pragma unroll
        for (int i = 0; i < 4; i++)
            #pragma unroll
            for (int j = 0; j < 4; j++) acc[i][j] += aa[i] * bb[j];
    }
    #pragma unroll
    for (int i = 0; i < 4; i++) {
        float4 w; w.x = acc[i][0]; w.y = acc[i][1]; w.z = acc[i][2]; w.w = acc[i][3];
        *(float4*)&g_part[kb * (ALPHA * DIM) + (ty * 4 + i) * DIM + d0 + tx * 4] = w;
    }
}

// ---------------- prep: reduce + convert ----------------
__global__ __launch_bounds__(256) void prep_reduce(
    const float* __restrict__ b_Q, const float* __restrict__ C_K,
    const float* __restrict__ C_V)
{
    __shared__ float red[256];
    const int tid = threadIdx.x;
    if (blockIdx.x == 256) {                         // bias block
        const int a = tid & 63, ks = tid >> 6;
        float s = 0.f;
        for (int e = ks * 256; e < ks * 256 + 256; e++)
            s += b_Q[e] * C_K[e * ALPHA + a];
        red[tid] = s;
        __syncthreads();
        if (tid < 64)
            g_bias[tid] = (red[tid] + red[tid + 64] + red[tid + 128] + red[tid + 192]) * SCALE;
        return;
    }
    const int o = blockIdx.x * 256 + tid;
    float s = 0.f;
    #pragma unroll
    for (int p = 0; p < 16; p++) s += g_part[p * (ALPHA * DIM) + o];
    g_Mth[o] = __float2half_rn(s * SCALE * MT_S);
    const float cv = C_V[o] * CV_S;
    const __half ch = __float2half_rn(cv);
    g_CVh[o] = ch;
    g_CVl[o] = __float2half_rn(cv - __half2float(ch));
}

// ---------------- fused: 1 CTA = 128 rows, 256 threads (8 warps 4rg x 2ng) ----------------
__global__ __launch_bounds__(256, 1) void fused_mma(
    const float* __restrict__ x, const int* __restrict__ mask,
    float* __restrict__ out)
{
    extern __shared__ __align__(16) char sm[];
    __half* xs  = (__half*)(sm + XS_OFF);
    __half* mts = (__half*)(sm + MTS_OFF);
    float*  ls  = (float*)(sm + LS_OFF);
    __half* ahs = (__half*)(sm + AH_OFF);
    __half* als = (__half*)(sm + AL_OFF);
    __half* cvh = (__half*)(sm + CVH_OFF);
    __half* cvl = (__half*)(sm + CVL_OFF);
    float*  bsm = (float*)(sm + BIAS_OFF);

    const int tid  = threadIdx.x;
    const int lane = tid & 31, wid = tid >> 5;
    const int gid  = lane >> 2, tig = lane & 3;
    const int rg   = wid >> 1, ng = wid & 1;
    const int row0 = blockIdx.x * TILE_ROWS;

    if (tid < ALPHA) bsm[tid] = g_bias[tid];

    // loader coords (shared by x and cv staging)
    const int lrow = tid >> 1, lk0 = (tid & 1) * 32;

    float4 xv[8];
    uint4  mtv[2];

    auto ldg_x = [&](int c) {
        const float* xp = x + (size_t)(row0 + lrow) * DIM + c * 64 + lk0;
        #pragma unroll
        for (int j = 0; j < 8; j++) xv[j] = *(const float4*)(xp + j * 4);
        const char* mb = (const char*)g_Mth;
        #pragma unroll
        for (int jj = 0; jj < 2; jj++) {
            const int j = tid * 2 + jj;
            mtv[jj] = *(const uint4*)(mb + (j >> 3) * 2048 + c * 128 + (j & 7) * 16);
        }
    };
    auto sts_x = [&]() {
        uint32_t hp[16];
        #pragma unroll
        for (int j = 0; j < 8; j++) {
            hp[2 * j]     = fpack(xv[j].x, xv[j].y);
            hp[2 * j + 1] = fpack(xv[j].z, xv[j].w);
        }
        uint4* xd = (uint4*)(xs + lrow * 72 + lk0);
        #pragma unroll
        for (int q = 0; q < 4; q++)
            xd[q] = make_uint4(hp[4 * q], hp[4 * q + 1], hp[4 * q + 2], hp[4 * q + 3]);
        #pragma unroll
        for (int jj = 0; jj < 2; jj++) {
            const int j = tid * 2 + jj;
            *(uint4*)((char*)mts + (j >> 3) * 144 + (j & 7) * 16) = mtv[jj];
        }
    };

    // ---- phase 1: logits = x @ Mt^T, 16 chunks of k=64 ----
    float acc1[2][4][4] = {};
    ldg_x(0);
    sts_x();
    __syncthreads();
    for (int c = 0; c < 16; c++) {
        if (c < 15) ldg_x(c + 1);
        #pragma unroll
        for (int ks = 0; ks < 4; ks++) {
            uint32_t A0[2][4];
            #pragma unroll
            for (int m = 0; m < 2; m++) {
                const __half* ap = xs + (rg * 32 + m * 16 + gid) * 72 + ks * 16 + tig * 2;
                A0[m][0] = *(const uint32_t*)ap;
                A0[m][1] = *(const uint32_t*)(ap + 8 * 72);
                A0[m][2] = *(const uint32_t*)(ap + 8);
                A0[m][3] = *(const uint32_t*)(ap + 8 * 72 + 8);
            }
            #pragma unroll
            for (int n = 0; n < 4; n++) {
                const __half* bp = mts + (ng * 32 + n * 8 + gid) * 72 + ks * 16 + tig * 2;
                uint32_t B0[2] = {*(const uint32_t*)bp, *(const uint32_t*)(bp + 8)};
                mma16816(acc1[0][n], A0[0], B0);
                mma16816(acc1[1][n], A0[1], B0);
            }
        }
        __syncthreads();
        if (c < 15) { sts_x(); __syncthreads(); }
    }

    // stash logits to ls (aliases xs; all warps past last mma)
    #pragma unroll
    for (int m = 0; m < 2; m++)
        #pragma unroll
        for (int n = 0; n < 4; n++) {
            const int r = rg * 32 + m * 16 + gid;
            const int cc = ng * 32 + n * 8 + tig * 2;
            float* p = ls + r * 68 + cc;
            p[0] = acc1[m][n][0];
            p[1] = acc1[m][n][1];
            p[8 * 68] = acc1[m][n][2];
            p[8 * 68 + 1] = acc1[m][n][3];
        }
    __syncthreads();

    // ---- phase 2: softmax * mask, emit A hi/lo fp16 (x A_S) ----
    if (tid < TILE_ROWS) {
        float e[64];
        const float* lp = ls + tid * 68;
        float mx = -1e30f;
        #pragma unroll
        for (int a = 0; a < 64; a++) {
            const float v = lp[a] * INV_MT + bsm[a];
            e[a] = v;
            mx = fmaxf(mx, v);
        }
        float s = 0.f;
        #pragma unroll
        for (int a = 0; a < 64; a++) { e[a] = __expf(e[a] - mx); s += e[a]; }
        const float inv = (mask[row0 + tid] ? A_S : 0.0f) / s;
        __half* ahp = ahs + tid * 72;
        __half* alp = als + tid * 72;
        #pragma unroll
        for (int a = 0; a < 64; a++) {
            const float p = e[a] * inv;
            const __half h = __float2half_rn(p);
            ahp[a] = h;
            alp[a] = __float2half_rn(p - __half2float(h));
        }
    }
    __syncthreads();

    // ---- phase 3: out = A @ C_V^T, 8 chunks of 128 d, 3-pass hi/lo ----
    uint32_t Ah[2][4][4];
    #pragma unroll
    for (int m = 0; m < 2; m++)
        #pragma unroll
        for (int ks = 0; ks < 4; ks++) {
            const __half* ap = ahs + (rg * 32 + m * 16 + gid) * 72 + ks * 16 + tig * 2;
            Ah[m][ks][0] = *(const uint32_t*)ap;
            Ah[m][ks][1] = *(const uint32_t*)(ap + 8 * 72);
            Ah[m][ks][2] = *(const uint32_t*)(ap + 8);
            Ah[m][ks][3] = *(const uint32_t*)(ap + 8 * 72 + 8);
        }

    uint4 cvvh[4], cvvl[4];
    auto ldg_cv = [&](int c) {
        const char* hb = (const char*)g_CVh;
        const char* lb = (const char*)g_CVl;
        const size_t base = (size_t)(c * 128 + lrow) * 128 + lk0 * 2;
        #pragma unroll
        for (int q = 0; q < 4; q++) {
            cvvh[q] = *(const uint4*)(hb + base + q * 16);
            cvvl[q] = *(const uint4*)(lb + base + q * 16);
        }
    };
    auto sts_cv = [&]() {
        uint4* dh = (uint4*)(cvh + lrow * 72 + lk0);
        uint4* dl = (uint4*)(cvl + lrow * 72 + lk0);
        #pragma unroll
        for (int q = 0; q < 4; q++) { dh[q] = cvvh[q]; dl[q] = cvvl[q]; }
    };

    ldg_cv(0);
    sts_cv();
    __syncthreads();
    for (int c = 0; c < 8; c++) {
        if (c < 7) ldg_cv(c + 1);
        float acc[2][8][4] = {};
        #pragma unroll
        for (int ks = 0; ks < 4; ks++) {
            uint32_t Al_[2][4];
            #pragma unroll
            for (int m = 0; m < 2; m++) {
                const __half* ap = als + (rg * 32 + m * 16 + gid) * 72 + ks * 16 + tig * 2;
                Al_[m][0] = *(const uint32_t*)ap;
                Al_[m][1] = *(const uint32_t*)(ap + 8 * 72);
                Al_[m][2] = *(const uint32_t*)(ap + 8);
                Al_[m][3] = *(const uint32_t*)(ap + 8 * 72 + 8);
            }
            #pragma unroll
            for (int n = 0; n < 8; n++) {
                const int brow = (ng * 64 + n * 8 + gid) * 72 + ks * 16 + tig * 2;
                const __half* bph = cvh + brow;
                const __half* bpl = cvl + brow;
                uint32_t Bh[2] = {*(const uint32_t*)bph, *(const uint32_t*)(bph + 8)};
                uint32_t Bl[2] = {*(const uint32_t*)bpl, *(const uint32_t*)(bpl + 8)};
                #pragma unroll
                for (int m = 0; m < 2; m++) {
                    mma16816(acc[m][n], Ah[m][ks], Bh);
                    mma16816(acc[m][n], Al_[m], Bh);
                    mma16816(acc[m][n], Ah[m][ks], Bl);
                }
            }
        }
        // store this d-chunk
        #pragma unroll
        for (int m = 0; m < 2; m++)
            #pragma unroll
            for (int n = 0; n < 8; n++) {
                const size_t r = (size_t)(row0 + rg * 32 + m * 16 + gid);
                const int d = c * 128 + ng * 64 + n * 8 + tig * 2;
                float* po = out + r * DIM + d;
                po[0] = acc[m][n][0] * OUT_S;
                po[1] = acc[m][n][1] * OUT_S;
                po[8 * DIM] = acc[m][n][2] * OUT_S;
                po[8 * DIM + 1] = acc[m][n][3] * OUT_S;
            }
        __syncthreads();
        if (c < 7) { sts_cv(); __syncthreads(); }
    }
}

// ---------------------------------------------------------------------------
extern "C" void kernel_launch(void* const* d_in, const int* in_sizes, int n_in,
                              void* d_out, int out_size)
{
    const float* x    = (const float*)d_in[0];
    const int*   mask = (const int*)d_in[1];
    const float* W_Q  = (const float*)d_in[2];
    const float* b_Q  = (const float*)d_in[3];
    const float* C_K  = (const float*)d_in[4];
    const float* C_V  = (const float*)d_in[5];
    float*       out  = (float*)d_out;

    cudaFuncSetAttribute(fused_mma, cudaFuncAttributeMaxDynamicSharedMemorySize, SMEM_BYTES);
    prep_partial<<<256, 256>>>(W_Q, C_K);
    prep_reduce<<<257, 256>>>(b_Q, C_K, C_V);
    fused_mma<<<NCTA, 256, SMEM_BYTES>>>(x, mask, out);
}

// round 6
// speedup vs baseline: 2.2742x; 1.0024x over previous
#include <cuda_runtime.h>
#include <cuda_fp16.h>
#include <cstdint>
#include <cstddef>

#define DIM    1024
#define ALPHA  64
#define NROWS  32768
#define SCALE  0.03125f        // 1/sqrt(1024)
#define TILE_ROWS 128
#define NCTA   (NROWS / TILE_ROWS)

// operand pre-scales (powers of 2, folded out exactly)
#define MT_S   256.0f
#define INV_MT (1.0f / 256.0f)
#define A_S    1024.0f
#define CV_S   64.0f
#define OUT_S  (1.0f / (1024.0f * 64.0f))

// smem layout (bytes). Aliasing by lifetime:
//   phase1: xs[128][72]h @0 (18432), mts[64][72]h @18432 (9216)
//   phase2: ls[128][68]f @0 (34816)  [xs/mts dead]
//   A:      ah[128][72]h @36864, al @55296 (alive through phase 3)
//   phase3: cvh[128][72]h @0, cvl @18432   [ls dead]
#define XS_OFF   0
#define MTS_OFF  18432
#define LS_OFF   0
#define AH_OFF   36864
#define AL_OFF   55296
#define CVH_OFF  0
#define CVL_OFF  18432
#define BIAS_OFF 73728
#define SMEM_BYTES 73984

__device__ float  g_part[16 * ALPHA * DIM];     // K-split partials for Mt
__device__ float  g_bias[ALPHA];
__device__ __half g_Mth[ALPHA * DIM];           // Mt[a][d] * 256, fp16
__device__ __half g_CVh[DIM * ALPHA];           // C_V[d][a]*64 hi
__device__ __half g_CVl[DIM * ALPHA];           // residual lo

// ---------------- helpers ----------------
__device__ __forceinline__ uint32_t fpack(float a, float b) {
    __half2 h = __floats2half2_rn(a, b);
    return *reinterpret_cast<uint32_t*>(&h);
}
__device__ __forceinline__ void mma16816(float* c, const uint32_t* a, const uint32_t* b) {
    asm volatile("mma.sync.aligned.m16n8k16.row.col.f32.f16.f16.f32 "
        "{%0,%1,%2,%3}, {%4,%5,%6,%7}, {%8,%9}, {%0,%1,%2,%3};"
        : "+f"(c[0]), "+f"(c[1]), "+f"(c[2]), "+f"(c[3])
        : "r"(a[0]), "r"(a[1]), "r"(a[2]), "r"(a[3]), "r"(b[0]), "r"(b[1]));
}

// ---------------- prep: partial GEMM  Mt_part = C_K^T @ W_Q (K-split 16x64) ----------------
__global__ __launch_bounds__(256) void prep_partial(
    const float* __restrict__ W_Q, const float* __restrict__ C_K)
{
    __shared__ float ck_s[64][68];
    __shared__ float wq_s[64][68];
    const int tid = threadIdx.x;
    const int nb = blockIdx.x & 15, kb = blockIdx.x >> 4;
    const int e0 = kb * 64, d0 = nb * 64;
    #pragma unroll
    for (int j = 0; j < 4; j++) {
        const int v = tid + 256 * j;
        const int e = v >> 4, q = v & 15;
        *(float4*)&ck_s[e][q * 4] = *(const float4*)&C_K[(e0 + e) * ALPHA + q * 4];
        *(float4*)&wq_s[e][q * 4] = *(const float4*)&W_Q[(size_t)(e0 + e) * DIM + d0 + q * 4];
    }
    __syncthreads();
    const int tx = tid & 15, ty = tid >> 4;
    float acc[4][4] = {};
    #pragma unroll 8
    for (int e = 0; e < 64; e++) {
        const float4 av = *(const float4*)&ck_s[e][ty * 4];
        const float4 bv = *(const float4*)&wq_s[e][tx * 4];
        const float aa[4] = {av.x, av.y, av.z, av.w};
        const float bb[4] = {bv.x, bv.y, bv.z, bv.w};
        #pragma unroll
        for (int i = 0; i < 4; i++)
            #pragma unroll
            for (int j = 0; j < 4; j++) acc[i][j] += aa[i] * bb[j];
    }
    #pragma unroll
    for (int i = 0; i < 4; i++) {
        float4 w; w.x = acc[i][0]; w.y = acc[i][1]; w.z = acc[i][2]; w.w = acc[i][3];
        *(float4*)&g_part[kb * (ALPHA * DIM) + (ty * 4 + i) * DIM + d0 + tx * 4] = w;
    }
}

// ---------------- prep: reduce + convert ----------------
__global__ __launch_bounds__(256) void prep_reduce(
    const float* __restrict__ b_Q, const float* __restrict__ C_K,
    const float* __restrict__ C_V)
{
    __shared__ float red[256];
    const int tid = threadIdx.x;
    if (blockIdx.x == 256) {                         // bias block
        const int a = tid & 63, ks = tid >> 6;
        float s = 0.f;
        for (int e = ks * 256; e < ks * 256 + 256; e++)
            s += b_Q[e] * C_K[e * ALPHA + a];
        red[tid] = s;
        __syncthreads();
        if (tid < 64)
            g_bias[tid] = (red[tid] + red[tid + 64] + red[tid + 128] + red[tid + 192]) * SCALE;
        return;
    }
    const int o = blockIdx.x * 256 + tid;
    float s = 0.f;
    #pragma unroll
    for (int p = 0; p < 16; p++) s += g_part[p * (ALPHA * DIM) + o];
    g_Mth[o] = __float2half_rn(s * SCALE * MT_S);
    const float cv = C_V[o] * CV_S;
    const __half ch = __float2half_rn(cv);
    g_CVh[o] = ch;
    g_CVl[o] = __float2half_rn(cv - __half2float(ch));
}

// ---------------- fused: 1 CTA = 128 rows, 256 threads (8 warps 4rg x 2ng) ----------------
__global__ __launch_bounds__(256, 1) void fused_mma(
    const float* __restrict__ x, const int* __restrict__ mask,
    float* __restrict__ out)
{
    extern __shared__ __align__(16) char sm[];
    __half* xs  = (__half*)(sm + XS_OFF);
    __half* mts = (__half*)(sm + MTS_OFF);
    float*  ls  = (float*)(sm + LS_OFF);
    __half* ahs = (__half*)(sm + AH_OFF);
    __half* als = (__half*)(sm + AL_OFF);
    __half* cvh = (__half*)(sm + CVH_OFF);
    __half* cvl = (__half*)(sm + CVL_OFF);
    float*  bsm = (float*)(sm + BIAS_OFF);

    const int tid  = threadIdx.x;
    const int lane = tid & 31, wid = tid >> 5;
    const int gid  = lane >> 2, tig = lane & 3;
    const int rg   = wid >> 1, ng = wid & 1;
    const int row0 = blockIdx.x * TILE_ROWS;

    if (tid < ALPHA) bsm[tid] = g_bias[tid];

    // loader coords (shared by x and cv staging)
    const int lrow = tid >> 1, lk0 = (tid & 1) * 32;

    float4 xv[8];
    uint4  mtv[2];

    auto ldg_x = [&](int c) {
        const float* xp = x + (size_t)(row0 + lrow) * DIM + c * 64 + lk0;
        #pragma unroll
        for (int j = 0; j < 8; j++) xv[j] = *(const float4*)(xp + j * 4);
        const char* mb = (const char*)g_Mth;
        #pragma unroll
        for (int jj = 0; jj < 2; jj++) {
            const int j = tid * 2 + jj;
            mtv[jj] = *(const uint4*)(mb + (j >> 3) * 2048 + c * 128 + (j & 7) * 16);
        }
    };
    auto sts_x = [&]() {
        uint32_t hp[16];
        #pragma unroll
        for (int j = 0; j < 8; j++) {
            hp[2 * j]     = fpack(xv[j].x, xv[j].y);
            hp[2 * j + 1] = fpack(xv[j].z, xv[j].w);
        }
        uint4* xd = (uint4*)(xs + lrow * 72 + lk0);
        #pragma unroll
        for (int q = 0; q < 4; q++)
            xd[q] = make_uint4(hp[4 * q], hp[4 * q + 1], hp[4 * q + 2], hp[4 * q + 3]);
        #pragma unroll
        for (int jj = 0; jj < 2; jj++) {
            const int j = tid * 2 + jj;
            *(uint4*)((char*)mts + (j >> 3) * 144 + (j & 7) * 16) = mtv[jj];
        }
    };

    // ---- phase 1: logits = x @ Mt^T, 16 chunks of k=64 ----
    float acc1[2][4][4] = {};
    ldg_x(0);
    sts_x();
    __syncthreads();
    for (int c = 0; c < 16; c++) {
        if (c < 15) ldg_x(c + 1);
        #pragma unroll
        for (int ks = 0; ks < 4; ks++) {
            uint32_t A0[2][4];
            #pragma unroll
            for (int m = 0; m < 2; m++) {
                const __half* ap = xs + (rg * 32 + m * 16 + gid) * 72 + ks * 16 + tig * 2;
                A0[m][0] = *(const uint32_t*)ap;
                A0[m][1] = *(const uint32_t*)(ap + 8 * 72);
                A0[m][2] = *(const uint32_t*)(ap + 8);
                A0[m][3] = *(const uint32_t*)(ap + 8 * 72 + 8);
            }
            #pragma unroll
            for (int n = 0; n < 4; n++) {
                const __half* bp = mts + (ng * 32 + n * 8 + gid) * 72 + ks * 16 + tig * 2;
                uint32_t B0[2] = {*(const uint32_t*)bp, *(const uint32_t*)(bp + 8)};
                mma16816(acc1[0][n], A0[0], B0);
                mma16816(acc1[1][n], A0[1], B0);
            }
        }
        __syncthreads();
        if (c < 15) { sts_x(); __syncthreads(); }
    }

    // stash logits to ls (aliases xs; all warps past last mma)
    #pragma unroll
    for (int m = 0; m < 2; m++)
        #pragma unroll
        for (int n = 0; n < 4; n++) {
            const int r = rg * 32 + m * 16 + gid;
            const int cc = ng * 32 + n * 8 + tig * 2;
            float* p = ls + r * 68 + cc;
            p[0] = acc1[m][n][0];
            p[1] = acc1[m][n][1];
            p[8 * 68] = acc1[m][n][2];
            p[8 * 68 + 1] = acc1[m][n][3];
        }
    __syncthreads();

    // ---- phase 2: softmax * mask, emit A hi/lo fp16 (x A_S) ----
    if (tid < TILE_ROWS) {
        float e[64];
        const float* lp = ls + tid * 68;
        float mx = -1e30f;
        #pragma unroll
        for (int a = 0; a < 64; a++) {
            const float v = lp[a] * INV_MT + bsm[a];
            e[a] = v;
            mx = fmaxf(mx, v);
        }
        float s = 0.f;
        #pragma unroll
        for (int a = 0; a < 64; a++) { e[a] = __expf(e[a] - mx); s += e[a]; }
        const float inv = (mask[row0 + tid] ? A_S : 0.0f) / s;
        __half* ahp = ahs + tid * 72;
        __half* alp = als + tid * 72;
        #pragma unroll
        for (int a = 0; a < 64; a++) {
            const float p = e[a] * inv;
            const __half h = __float2half_rn(p);
            ahp[a] = h;
            alp[a] = __float2half_rn(p - __half2float(h));
        }
    }
    __syncthreads();

    // ---- phase 3: out = A @ C_V^T, 8 chunks of 128 d, 3-pass hi/lo ----
    uint32_t Ah[2][4][4];
    #pragma unroll
    for (int m = 0; m < 2; m++)
        #pragma unroll
        for (int ks = 0; ks < 4; ks++) {
            const __half* ap = ahs + (rg * 32 + m * 16 + gid) * 72 + ks * 16 + tig * 2;
            Ah[m][ks][0] = *(const uint32_t*)ap;
            Ah[m][ks][1] = *(const uint32_t*)(ap + 8 * 72);
            Ah[m][ks][2] = *(const uint32_t*)(ap + 8);
            Ah[m][ks][3] = *(const uint32_t*)(ap + 8 * 72 + 8);
        }

    uint4 cvvh[4], cvvl[4];
    auto ldg_cv = [&](int c) {
        const char* hb = (const char*)g_CVh;
        const char* lb = (const char*)g_CVl;
        const size_t base = (size_t)(c * 128 + lrow) * 128 + lk0 * 2;
        #pragma unroll
        for (int q = 0; q < 4; q++) {
            cvvh[q] = *(const uint4*)(hb + base + q * 16);
            cvvl[q] = *(const uint4*)(lb + base + q * 16);
        }
    };
    auto sts_cv = [&]() {
        uint4* dh = (uint4*)(cvh + lrow * 72 + lk0);
        uint4* dl = (uint4*)(cvl + lrow * 72 + lk0);
        #pragma unroll
        for (int q = 0; q < 4; q++) { dh[q] = cvvh[q]; dl[q] = cvvl[q]; }
    };

    ldg_cv(0);
    sts_cv();
    __syncthreads();
    for (int c = 0; c < 8; c++) {
        if (c < 7) ldg_cv(c + 1);
        float acc[2][8][4] = {};
        #pragma unroll
        for (int ks = 0; ks < 4; ks++) {
            uint32_t Al_[2][4];
            #pragma unroll
            for (int m = 0; m < 2; m++) {
                const __half* ap = als + (rg * 32 + m * 16 + gid) * 72 + ks * 16 + tig * 2;
                Al_[m][0] = *(const uint32_t*)ap;
                Al_[m][1] = *(const uint32_t*)(ap + 8 * 72);
                Al_[m][2] = *(const uint32_t*)(ap + 8);
                Al_[m][3] = *(const uint32_t*)(ap + 8 * 72 + 8);
            }
            #pragma unroll
            for (int n = 0; n < 8; n++) {
                const int brow = (ng * 64 + n * 8 + gid) * 72 + ks * 16 + tig * 2;
                const __half* bph = cvh + brow;
                const __half* bpl = cvl + brow;
                uint32_t Bh[2] = {*(const uint32_t*)bph, *(const uint32_t*)(bph + 8)};
                uint32_t Bl[2] = {*(const uint32_t*)bpl, *(const uint32_t*)(bpl + 8)};
                #pragma unroll
                for (int m = 0; m < 2; m++) {
                    mma16816(acc[m][n], Ah[m][ks], Bh);
                    mma16816(acc[m][n], Al_[m], Bh);
                    mma16816(acc[m][n], Ah[m][ks], Bl);
                }
            }
        }
        // store this d-chunk
        #pragma unroll
        for (int m = 0; m < 2; m++)
            #pragma unroll
            for (int n = 0; n < 8; n++) {
                const size_t r = (size_t)(row0 + rg * 32 + m * 16 + gid);
                const int d = c * 128 + ng * 64 + n * 8 + tig * 2;
                float* po = out + r * DIM + d;
                po[0] = acc[m][n][0] * OUT_S;
                po[1] = acc[m][n][1] * OUT_S;
                po[8 * DIM] = acc[m][n][2] * OUT_S;
                po[8 * DIM + 1] = acc[m][n][3] * OUT_S;
            }
        __syncthreads();
        if (c < 7) { sts_cv(); __syncthreads(); }
    }
}

// ---------------------------------------------------------------------------
extern "C" void kernel_launch(void* const* d_in, const int* in_sizes, int n_in,
                              void* d_out, int out_size)
{
    const float* x    = (const float*)d_in[0];
    const int*   mask = (const int*)d_in[1];
    const float* W_Q  = (const float*)d_in[2];
    const float* b_Q  = (const float*)d_in[3];
    const float* C_K  = (const float*)d_in[4];
    const float* C_V  = (const float*)d_in[5];
    float*       out  = (float*)d_out;

    cudaFuncSetAttribute(fused_mma, cudaFuncAttributeMaxDynamicSharedMemorySize, SMEM_BYTES);
    prep_partial<<<256, 256>>>(W_Q, C_K);
    prep_reduce<<<257, 256>>>(b_Q, C_K, C_V);
    fused_mma<<<NCTA, 256, SMEM_BYTES>>>(x, mask, out);
}

// round 7
// speedup vs baseline: 2.7138x; 1.1933x over previous
#include <cuda_runtime.h>
#include <cuda_fp16.h>
#include <cstdint>
#include <cstddef>

#define DIM    1024
#define ALPHA  64
#define NROWS  32768
#define SCALE  0.03125f        // 1/sqrt(1024)
#define TILE_ROWS 128
#define NCTA   (NROWS / TILE_ROWS)

// operand pre-scales (powers of 2, folded out exactly)
#define MT_S   256.0f
#define INV_MT (1.0f / 256.0f)
#define A_S    1024.0f
#define CV_S   64.0f
#define OUT_S  (1.0f / (1024.0f * 64.0f))

// smem layout (bytes), aliased by lifetime:
//   phase1: xs[128][72]h @0 (18432), mts[64][72]h @18432 (9216)
//   phase2: ls[128][68]f @0 (34816)            [xs/mts dead]
//   A hi:   ahs[128][72]h @34816 (18432)       [alive thru phase3]
//   phase3: cvh[64][72]h @0 (9216), cvl @9216  [ls dead]
#define XS_OFF   0
#define MTS_OFF  18432
#define LS_OFF   0
#define AH_OFF   34816
#define CVH_OFF  0
#define CVL_OFF  9216
#define BIAS_OFF 53248
#define SMEM_BYTES 53504

__device__ float  g_part[16 * ALPHA * DIM];     // K-split partials for Mt
__device__ float  g_bias[ALPHA];
__device__ __half g_Mth[ALPHA * DIM];           // Mt[a][d] * 256, fp16
__device__ __half g_CVh[DIM * ALPHA];           // C_V[d][a]*64 hi
__device__ __half g_CVl[DIM * ALPHA];           // residual lo

// ---------------- helpers ----------------
__device__ __forceinline__ uint32_t fpack(float a, float b) {
    __half2 h = __floats2half2_rn(a, b);
    return *reinterpret_cast<uint32_t*>(&h);
}
__device__ __forceinline__ void mma16816(float* c, const uint32_t* a, const uint32_t* b) {
    asm volatile("mma.sync.aligned.m16n8k16.row.col.f32.f16.f16.f32 "
        "{%0,%1,%2,%3}, {%4,%5,%6,%7}, {%8,%9}, {%0,%1,%2,%3};"
        : "+f"(c[0]), "+f"(c[1]), "+f"(c[2]), "+f"(c[3])
        : "r"(a[0]), "r"(a[1]), "r"(a[2]), "r"(a[3]), "r"(b[0]), "r"(b[1]));
}

// ---------------- prep: partial GEMM  Mt_part = C_K^T @ W_Q (K-split 16x64) ----------------
__global__ __launch_bounds__(256) void prep_partial(
    const float* __restrict__ W_Q, const float* __restrict__ C_K)
{
    __shared__ float ck_s[64][68];
    __shared__ float wq_s[64][68];
    const int tid = threadIdx.x;
    const int nb = blockIdx.x & 15, kb = blockIdx.x >> 4;
    const int e0 = kb * 64, d0 = nb * 64;
    #pragma unroll
    for (int j = 0; j < 4; j++) {
        const int v = tid + 256 * j;
        const int e = v >> 4, q = v & 15;
        *(float4*)&ck_s[e][q * 4] = *(const float4*)&C_K[(e0 + e) * ALPHA + q * 4];
        *(float4*)&wq_s[e][q * 4] = *(const float4*)&W_Q[(size_t)(e0 + e) * DIM + d0 + q * 4];
    }
    __syncthreads();
    const int tx = tid & 15, ty = tid >> 4;
    float acc[4][4] = {};
    #pragma unroll 8
    for (int e = 0; e < 64; e++) {
        const float4 av = *(const float4*)&ck_s[e][ty * 4];
        const float4 bv = *(const float4*)&wq_s[e][tx * 4];
        const float aa[4] = {av.x, av.y, av.z, av.w};
        const float bb[4] = {bv.x, bv.y, bv.z, bv.w};
        #pragma unroll
        for (int i = 0; i < 4; i++)
            #pragma unroll
            for (int j = 0; j < 4; j++) acc[i][j] += aa[i] * bb[j];
    }
    #pragma unroll
    for (int i = 0; i < 4; i++) {
        float4 w; w.x = acc[i][0]; w.y = acc[i][1]; w.z = acc[i][2]; w.w = acc[i][3];
        *(float4*)&g_part[kb * (ALPHA * DIM) + (ty * 4 + i) * DIM + d0 + tx * 4] = w;
    }
}

// ---------------- prep: reduce + convert ----------------
__global__ __launch_bounds__(256) void prep_reduce(
    const float* __restrict__ b_Q, const float* __restrict__ C_K,
    const float* __restrict__ C_V)
{
    __shared__ float red[256];
    const int tid = threadIdx.x;
    if (blockIdx.x == 256) {                         // bias block
        const int a = tid & 63, ks = tid >> 6;
        float s = 0.f;
        for (int e = ks * 256; e < ks * 256 + 256; e++)
            s += b_Q[e] * C_K[e * ALPHA + a];
        red[tid] = s;
        __syncthreads();
        if (tid < 64)
            g_bias[tid] = (red[tid] + red[tid + 64] + red[tid + 128] + red[tid + 192]) * SCALE;
        return;
    }
    const int o = blockIdx.x * 256 + tid;
    float s = 0.f;
    #pragma unroll
    for (int p = 0; p < 16; p++) s += g_part[p * (ALPHA * DIM) + o];
    g_Mth[o] = __float2half_rn(s * SCALE * MT_S);
    const float cv = C_V[o] * CV_S;
    const __half ch = __float2half_rn(cv);
    g_CVh[o] = ch;
    g_CVl[o] = __float2half_rn(cv - __half2float(ch));
}

// ---------------- fused: 1 CTA = 128 rows, 256 threads, 2 CTAs/SM ----------------
__global__ __launch_bounds__(256, 2) void fused_mma(
    const float* __restrict__ x, const int* __restrict__ mask,
    float* __restrict__ out)
{
    extern __shared__ __align__(16) char sm[];
    __half* xs  = (__half*)(sm + XS_OFF);
    __half* mts = (__half*)(sm + MTS_OFF);
    float*  ls  = (float*)(sm + LS_OFF);
    __half* ahs = (__half*)(sm + AH_OFF);
    __half* cvh = (__half*)(sm + CVH_OFF);
    __half* cvl = (__half*)(sm + CVL_OFF);
    float*  bsm = (float*)(sm + BIAS_OFF);

    const int tid  = threadIdx.x;
    const int lane = tid & 31, wid = tid >> 5;
    const int gid  = lane >> 2, tig = lane & 3;
    const int rg   = wid >> 1, ng = wid & 1;
    const int row0 = blockIdx.x * TILE_ROWS;

    if (tid < ALPHA) bsm[tid] = g_bias[tid];

    // x loader coords
    const int lrow = tid >> 1, lk0 = (tid & 1) * 32;

    float4 xv[8];
    uint4  mtv[2];

    auto ldg_x = [&](int c) {
        const float* xp = x + (size_t)(row0 + lrow) * DIM + c * 64 + lk0;
        #pragma unroll
        for (int j = 0; j < 8; j++) xv[j] = *(const float4*)(xp + j * 4);
        const char* mb = (const char*)g_Mth;
        #pragma unroll
        for (int jj = 0; jj < 2; jj++) {
            const int j = tid * 2 + jj;
            mtv[jj] = *(const uint4*)(mb + (j >> 3) * 2048 + c * 128 + (j & 7) * 16);
        }
    };
    auto sts_x = [&]() {
        uint32_t hp[16];
        #pragma unroll
        for (int j = 0; j < 8; j++) {
            hp[2 * j]     = fpack(xv[j].x, xv[j].y);
            hp[2 * j + 1] = fpack(xv[j].z, xv[j].w);
        }
        uint4* xd = (uint4*)(xs + lrow * 72 + lk0);
        #pragma unroll
        for (int q = 0; q < 4; q++)
            xd[q] = make_uint4(hp[4 * q], hp[4 * q + 1], hp[4 * q + 2], hp[4 * q + 3]);
        #pragma unroll
        for (int jj = 0; jj < 2; jj++) {
            const int j = tid * 2 + jj;
            *(uint4*)((char*)mts + (j >> 3) * 144 + (j & 7) * 16) = mtv[jj];
        }
    };

    // ---- phase 1: logits = x @ Mt^T, 16 chunks of k=64 ----
    float acc1[2][4][4] = {};
    ldg_x(0);
    sts_x();
    __syncthreads();
    for (int c = 0; c < 16; c++) {
        if (c < 15) ldg_x(c + 1);
        #pragma unroll
        for (int ks = 0; ks < 4; ks++) {
            uint32_t A0[2][4];
            #pragma unroll
            for (int m = 0; m < 2; m++) {
                const __half* ap = xs + (rg * 32 + m * 16 + gid) * 72 + ks * 16 + tig * 2;
                A0[m][0] = *(const uint32_t*)ap;
                A0[m][1] = *(const uint32_t*)(ap + 8 * 72);
                A0[m][2] = *(const uint32_t*)(ap + 8);
                A0[m][3] = *(const uint32_t*)(ap + 8 * 72 + 8);
            }
            #pragma unroll
            for (int n = 0; n < 4; n++) {
                const __half* bp = mts + (ng * 32 + n * 8 + gid) * 72 + ks * 16 + tig * 2;
                uint32_t B0[2] = {*(const uint32_t*)bp, *(const uint32_t*)(bp + 8)};
                mma16816(acc1[0][n], A0[0], B0);
                mma16816(acc1[1][n], A0[1], B0);
            }
        }
        __syncthreads();
        if (c < 15) { sts_x(); __syncthreads(); }
    }

    // stash logits to ls (aliases xs/mts; all warps past last mma)
    #pragma unroll
    for (int m = 0; m < 2; m++)
        #pragma unroll
        for (int n = 0; n < 4; n++) {
            const int r = rg * 32 + m * 16 + gid;
            const int cc = ng * 32 + n * 8 + tig * 2;
            float* p = ls + r * 68 + cc;
            p[0] = acc1[m][n][0];
            p[1] = acc1[m][n][1];
            p[8 * 68] = acc1[m][n][2];
            p[8 * 68 + 1] = acc1[m][n][3];
        }
    __syncthreads();

    // ---- phase 2: softmax * mask, emit A fp16 (x A_S) ----
    if (tid < TILE_ROWS) {
        float e[64];
        const float* lp = ls + tid * 68;
        float mx = -1e30f;
        #pragma unroll
        for (int a = 0; a < 64; a++) {
            const float v = lp[a] * INV_MT + bsm[a];
            e[a] = v;
            mx = fmaxf(mx, v);
        }
        float s = 0.f;
        #pragma unroll
        for (int a = 0; a < 64; a++) { e[a] = __expf(e[a] - mx); s += e[a]; }
        const float inv = (mask[row0 + tid] ? A_S : 0.0f) / s;
        __half* ahp = ahs + tid * 72;
        #pragma unroll
        for (int a = 0; a < 64; a++)
            ahp[a] = __float2half_rn(e[a] * inv);
    }
    __syncthreads();

    // ---- phase 3: out = A @ C_V^T, 16 chunks of 64 d, 2-pass (A·CVh + A·CVl) ----
    uint32_t Ah[2][4][4];
    #pragma unroll
    for (int m = 0; m < 2; m++)
        #pragma unroll
        for (int ks = 0; ks < 4; ks++) {
            const __half* ap = ahs + (rg * 32 + m * 16 + gid) * 72 + ks * 16 + tig * 2;
            Ah[m][ks][0] = *(const uint32_t*)ap;
            Ah[m][ks][1] = *(const uint32_t*)(ap + 8 * 72);
            Ah[m][ks][2] = *(const uint32_t*)(ap + 8);
            Ah[m][ks][3] = *(const uint32_t*)(ap + 8 * 72 + 8);
        }

    // C_V loader: 64 d-rows per chunk, 256 threads, 32B hi + 32B lo each
    const int brow = tid >> 2, bseg = (tid & 3) * 16;   // halves
    uint4 cvvh[2], cvvl[2];
    auto ldg_cv = [&](int c) {
        const char* hb = (const char*)g_CVh;
        const char* lb = (const char*)g_CVl;
        const size_t base = (size_t)(c * 64 + brow) * 128 + bseg * 2;
        cvvh[0] = *(const uint4*)(hb + base);
        cvvh[1] = *(const uint4*)(hb + base + 16);
        cvvl[0] = *(const uint4*)(lb + base);
        cvvl[1] = *(const uint4*)(lb + base + 16);
    };
    auto sts_cv = [&]() {
        uint4* dh = (uint4*)(cvh + brow * 72 + bseg);
        uint4* dl = (uint4*)(cvl + brow * 72 + bseg);
        dh[0] = cvvh[0]; dh[1] = cvvh[1];
        dl[0] = cvvl[0]; dl[1] = cvvl[1];
    };

    ldg_cv(0);
    sts_cv();
    __syncthreads();
    for (int c = 0; c < 16; c++) {
        if (c < 15) ldg_cv(c + 1);
        float acc[2][4][4] = {};
        #pragma unroll
        for (int ks = 0; ks < 4; ks++) {
            #pragma unroll
            for (int n = 0; n < 4; n++) {
                const int br = (ng * 32 + n * 8 + gid) * 72 + ks * 16 + tig * 2;
                const __half* bph = cvh + br;
                const __half* bpl = cvl + br;
                uint32_t Bh[2] = {*(const uint32_t*)bph, *(const uint32_t*)(bph + 8)};
                uint32_t Bl[2] = {*(const uint32_t*)bpl, *(const uint32_t*)(bpl + 8)};
                #pragma unroll
                for (int m = 0; m < 2; m++) {
                    mma16816(acc[m][n], Ah[m][ks], Bh);
                    mma16816(acc[m][n], Ah[m][ks], Bl);
                }
            }
        }
        // store this d-chunk
        #pragma unroll
        for (int m = 0; m < 2; m++)
            #pragma unroll
            for (int n = 0; n < 4; n++) {
                const size_t r = (size_t)(row0 + rg * 32 + m * 16 + gid);
                const int d = c * 64 + ng * 32 + n * 8 + tig * 2;
                float* po = out + r * DIM + d;
                po[0] = acc[m][n][0] * OUT_S;
                po[1] = acc[m][n][1] * OUT_S;
                po[8 * DIM] = acc[m][n][2] * OUT_S;
                po[8 * DIM + 1] = acc[m][n][3] * OUT_S;
            }
        __syncthreads();
        if (c < 15) { sts_cv(); __syncthreads(); }
    }
}

// ---------------------------------------------------------------------------
extern "C" void kernel_launch(void* const* d_in, const int* in_sizes, int n_in,
                              void* d_out, int out_size)
{
    const float* x    = (const float*)d_in[0];
    const int*   mask = (const int*)d_in[1];
    const float* W_Q  = (const float*)d_in[2];
    const float* b_Q  = (const float*)d_in[3];
    const float* C_K  = (const float*)d_in[4];
    const float* C_V  = (const float*)d_in[5];
    float*       out  = (float*)d_out;

    cudaFuncSetAttribute(fused_mma, cudaFuncAttributeMaxDynamicSharedMemorySize, SMEM_BYTES);
    prep_partial<<<256, 256>>>(W_Q, C_K);
    prep_reduce<<<257, 256>>>(b_Q, C_K, C_V);
    fused_mma<<<NCTA, 256, SMEM_BYTES>>>(x, mask, out);
}

// round 8
// speedup vs baseline: 2.8546x; 1.0519x over previous
#include <cuda_runtime.h>
#include <cuda_fp16.h>
#include <cstdint>
#include <cstddef>

#define DIM    1024
#define ALPHA  64
#define NROWS  32768
#define SCALE  0.03125f        // 1/sqrt(1024)
#define TILE_ROWS 128
#define NCTA   (NROWS / TILE_ROWS)

// operand pre-scales (powers of 2, folded out exactly)
#define MT_S   256.0f
#define INV_MT (1.0f / 256.0f)
#define A_S    1024.0f
#define CV_S   64.0f
#define OUT_S  (1.0f / (1024.0f * 64.0f))

// smem layout (bytes), aliased by lifetime:
//   phase1: xs[2][128][72]h @0 (36864), mts[2][64][72]h @36864 (18432)
//   phase2: ls[128][68]f @0 (34816)                 [xs dead, mma(15) synced]
//   A hi:   ahs[128][72]h @55296 (18432)            [alive thru phase3]
//   phase3: cvh[2]/cvl[2] 4x9216 @0                 [ls dead]
#define XS_OFF   0
#define MTS_OFF  36864
#define LS_OFF   0
#define AH_OFF   55296
#define CV_OFF   0
#define BIAS_OFF 73728
#define SMEM_BYTES 73984

#define KSPLIT 32
__device__ float  g_part[KSPLIT * ALPHA * DIM];
__device__ float  g_bias[ALPHA];
__device__ __half g_Mth[ALPHA * DIM];           // Mt[a][d] * 256
__device__ __half g_CVh[DIM * ALPHA];           // C_V[d][a]*64 hi
__device__ __half g_CVl[DIM * ALPHA];           // residual lo

// ---------------- helpers ----------------
__device__ __forceinline__ uint32_t fpack(float a, float b) {
    __half2 h = __floats2half2_rn(a, b);
    return *reinterpret_cast<uint32_t*>(&h);
}
__device__ __forceinline__ void mma16816(float* c, const uint32_t* a, const uint32_t* b) {
    asm volatile("mma.sync.aligned.m16n8k16.row.col.f32.f16.f16.f32 "
        "{%0,%1,%2,%3}, {%4,%5,%6,%7}, {%8,%9}, {%0,%1,%2,%3};"
        : "+f"(c[0]), "+f"(c[1]), "+f"(c[2]), "+f"(c[3])
        : "r"(a[0]), "r"(a[1]), "r"(a[2]), "r"(a[3]), "r"(b[0]), "r"(b[1]));
}
__device__ __forceinline__ void ldsm_x4(uint32_t* r, const __half* p) {
    uint32_t a = (uint32_t)__cvta_generic_to_shared(p);
    asm volatile("ldmatrix.sync.aligned.m8n8.x4.shared.b16 {%0,%1,%2,%3}, [%4];"
        : "=r"(r[0]), "=r"(r[1]), "=r"(r[2]), "=r"(r[3]) : "r"(a));
}

// ---------------- prep: partial GEMM  Mt_part = C_K^T @ W_Q (K-split 32x32) ----------------
__global__ __launch_bounds__(256) void prep_partial(
    const float* __restrict__ W_Q, const float* __restrict__ C_K)
{
    __shared__ float ck_s[32][68];
    __shared__ float wq_s[32][68];
    const int tid = threadIdx.x;
    const int nb = blockIdx.x & 15, kb = blockIdx.x >> 4;
    const int e0 = kb * 32, d0 = nb * 64;
    #pragma unroll
    for (int j = 0; j < 2; j++) {
        const int v = tid + 256 * j;
        const int e = v >> 4, q = v & 15;
        *(float4*)&ck_s[e][q * 4] = *(const float4*)&C_K[(e0 + e) * ALPHA + q * 4];
        *(float4*)&wq_s[e][q * 4] = *(const float4*)&W_Q[(size_t)(e0 + e) * DIM + d0 + q * 4];
    }
    __syncthreads();
    const int tx = tid & 15, ty = tid >> 4;
    float acc[4][4] = {};
    #pragma unroll 8
    for (int e = 0; e < 32; e++) {
        const float4 av = *(const float4*)&ck_s[e][ty * 4];
        const float4 bv = *(const float4*)&wq_s[e][tx * 4];
        const float aa[4] = {av.x, av.y, av.z, av.w};
        const float bb[4] = {bv.x, bv.y, bv.z, bv.w};
        #pragma unroll
        for (int i = 0; i < 4; i++)
            #pragma unroll
            for (int j = 0; j < 4; j++) acc[i][j] += aa[i] * bb[j];
    }
    #pragma unroll
    for (int i = 0; i < 4; i++) {
        float4 w; w.x = acc[i][0]; w.y = acc[i][1]; w.z = acc[i][2]; w.w = acc[i][3];
        *(float4*)&g_part[kb * (ALPHA * DIM) + (ty * 4 + i) * DIM + d0 + tx * 4] = w;
    }
}

// ---------------- prep: reduce + convert ----------------
__global__ __launch_bounds__(256) void prep_reduce(
    const float* __restrict__ b_Q, const float* __restrict__ C_K,
    const float* __restrict__ C_V)
{
    __shared__ float red[256];
    const int tid = threadIdx.x;
    if (blockIdx.x == 256) {                         // bias block
        const int a = tid & 63, ks = tid >> 6;
        float s = 0.f;
        for (int e = ks * 256; e < ks * 256 + 256; e++)
            s += b_Q[e] * C_K[e * ALPHA + a];
        red[tid] = s;
        __syncthreads();
        if (tid < 64)
            g_bias[tid] = (red[tid] + red[tid + 64] + red[tid + 128] + red[tid + 192]) * SCALE;
        return;
    }
    const int o = blockIdx.x * 256 + tid;
    float s = 0.f;
    #pragma unroll
    for (int p = 0; p < KSPLIT; p++) s += g_part[p * (ALPHA * DIM) + o];
    g_Mth[o] = __float2half_rn(s * SCALE * MT_S);
    const float cv = C_V[o] * CV_S;
    const __half ch = __float2half_rn(cv);
    g_CVh[o] = ch;
    g_CVl[o] = __float2half_rn(cv - __half2float(ch));
}

// ---------------- fused: 1 CTA = 128 rows, 256 threads, 2 CTAs/SM ----------------
__global__ __launch_bounds__(256, 2) void fused_mma(
    const float* __restrict__ x, const int* __restrict__ mask,
    float* __restrict__ out)
{
    extern __shared__ __align__(16) char sm[];
    __half* xs  = (__half*)(sm + XS_OFF);            // 2 bufs of 128*72
    __half* mts = (__half*)(sm + MTS_OFF);           // 2 bufs of 64*72
    float*  ls  = (float*)(sm + LS_OFF);
    __half* ahs = (__half*)(sm + AH_OFF);
    __half* cvs = (__half*)(sm + CV_OFF);            // [buf][hi/lo] 4 x 64*72
    float*  bsm = (float*)(sm + BIAS_OFF);

    const int tid  = threadIdx.x;
    const int lane = tid & 31, wid = tid >> 5;
    const int gid  = lane >> 2, tig = lane & 3;
    const int rg   = wid >> 1, ng = wid & 1;
    const int row0 = blockIdx.x * TILE_ROWS;

    if (tid < ALPHA) bsm[tid] = g_bias[tid];

    // ldmatrix per-lane coords
    const int arow = rg * 32 + (lane & 15);          // A-frag rows (+ m*16)
    const int acol = (lane >> 4) * 8;                // A-frag k sub-offset
    const int brow = ng * 32 + (lane & 7) + ((lane >> 4) & 1) * 8;  // B rows (+ nt*16)
    const int bcol = ((lane >> 3) & 1) * 8;          // B k sub-offset

    // loader coords
    const int lrow = tid >> 1, lk0 = (tid & 1) * 32;

    float4 xv[8];
    uint4  mtv[2];

    auto ldg_x = [&](int c) {
        const float* xp = x + (size_t)(row0 + lrow) * DIM + c * 64 + lk0;
        #pragma unroll
        for (int j = 0; j < 8; j++) xv[j] = *(const float4*)(xp + j * 4);
        const char* mb = (const char*)g_Mth;
        #pragma unroll
        for (int jj = 0; jj < 2; jj++) {
            const int j = tid * 2 + jj;
            mtv[jj] = *(const uint4*)(mb + (j >> 3) * 2048 + c * 128 + (j & 7) * 16);
        }
    };
    auto sts_x = [&](int b) {
        uint32_t hp[16];
        #pragma unroll
        for (int j = 0; j < 8; j++) {
            hp[2 * j]     = fpack(xv[j].x, xv[j].y);
            hp[2 * j + 1] = fpack(xv[j].z, xv[j].w);
        }
        uint4* xd = (uint4*)(xs + b * (128 * 72) + lrow * 72 + lk0);
        #pragma unroll
        for (int q = 0; q < 4; q++)
            xd[q] = make_uint4(hp[4 * q], hp[4 * q + 1], hp[4 * q + 2], hp[4 * q + 3]);
        char* md = (char*)(mts + b * (64 * 72));
        #pragma unroll
        for (int jj = 0; jj < 2; jj++) {
            const int j = tid * 2 + jj;
            *(uint4*)(md + (j >> 3) * 144 + (j & 7) * 16) = mtv[jj];
        }
    };

    // ---- phase 1: logits = x @ Mt^T, 16 chunks of k=64, double-buffered ----
    float acc1[2][4][4] = {};
    ldg_x(0);
    sts_x(0);
    __syncthreads();
    ldg_x(1);
    for (int c = 0; c < 16; c++) {
        const __half* xb = xs + (c & 1) * (128 * 72);
        const __half* mbf = mts + (c & 1) * (64 * 72);
        #pragma unroll
        for (int ks = 0; ks < 4; ks++) {
            uint32_t A0[2][4], B0[2][4];
            #pragma unroll
            for (int m = 0; m < 2; m++)
                ldsm_x4(A0[m], xb + (arow + m * 16) * 72 + ks * 16 + acol);
            #pragma unroll
            for (int nt = 0; nt < 2; nt++)
                ldsm_x4(B0[nt], mbf + (brow + nt * 16) * 72 + ks * 16 + bcol);
            #pragma unroll
            for (int nt = 0; nt < 2; nt++)
                #pragma unroll
                for (int m = 0; m < 2; m++) {
                    mma16816(acc1[m][nt * 2],     A0[m], &B0[nt][0]);
                    mma16816(acc1[m][nt * 2 + 1], A0[m], &B0[nt][2]);
                }
        }
        if (c < 15) sts_x((c + 1) & 1);
        __syncthreads();
        if (c < 14) ldg_x(c + 2);
    }

    // stash logits to ls (aliases xs; last sync covers mma(15))
    #pragma unroll
    for (int m = 0; m < 2; m++)
        #pragma unroll
        for (int n = 0; n < 4; n++) {
            const int r = rg * 32 + m * 16 + gid;
            const int cc = ng * 32 + n * 8 + tig * 2;
            float* p = ls + r * 68 + cc;
            p[0] = acc1[m][n][0];
            p[1] = acc1[m][n][1];
            p[8 * 68] = acc1[m][n][2];
            p[8 * 68 + 1] = acc1[m][n][3];
        }
    __syncthreads();

    // ---- phase 2: softmax * mask, emit A fp16 (x A_S) ----
    if (tid < TILE_ROWS) {
        float e[64];
        const float* lp = ls + tid * 68;
        float mx = -1e30f;
        #pragma unroll
        for (int a = 0; a < 64; a++) {
            const float v = lp[a] * INV_MT + bsm[a];
            e[a] = v;
            mx = fmaxf(mx, v);
        }
        float s = 0.f;
        #pragma unroll
        for (int a = 0; a < 64; a++) { e[a] = __expf(e[a] - mx); s += e[a]; }
        const float inv = (mask[row0 + tid] ? A_S : 0.0f) / s;
        __half* ahp = ahs + tid * 72;
        #pragma unroll
        for (int a = 0; a < 64; a++)
            ahp[a] = __float2half_rn(e[a] * inv);
    }
    __syncthreads();

    // ---- phase 3: out = A @ C_V^T, 16 chunks of 64 d, hi+lo, double-buffered ----
    uint32_t Ah[2][4][4];
    #pragma unroll
    for (int m = 0; m < 2; m++)
        #pragma unroll
        for (int ks = 0; ks < 4; ks++)
            ldsm_x4(Ah[m][ks], ahs + (arow + m * 16) * 72 + ks * 16 + acol);

    // C_V loader: 64 d-rows per chunk (hi+lo 32B each per thread)
    const int crow = tid >> 2, cseg = (tid & 3) * 16;
    uint4 cvvh[2], cvvl[2];
    auto ldg_cv = [&](int c) {
        const char* hb = (const char*)g_CVh;
        const char* lb = (const char*)g_CVl;
        const size_t base = (size_t)(c * 64 + crow) * 128 + cseg * 2;
        cvvh[0] = *(const uint4*)(hb + base);
        cvvh[1] = *(const uint4*)(hb + base + 16);
        cvvl[0] = *(const uint4*)(lb + base);
        cvvl[1] = *(const uint4*)(lb + base + 16);
    };
    auto sts_cv = [&](int b) {
        uint4* dh = (uint4*)(cvs + b * 2 * (64 * 72) + crow * 72 + cseg);
        uint4* dl = (uint4*)(cvs + (b * 2 + 1) * (64 * 72) + crow * 72 + cseg);
        dh[0] = cvvh[0]; dh[1] = cvvh[1];
        dl[0] = cvvl[0]; dl[1] = cvvl[1];
    };

    ldg_cv(0);
    sts_cv(0);
    __syncthreads();
    ldg_cv(1);
    for (int c = 0; c < 16; c++) {
        const __half* ch = cvs + (c & 1) * 2 * (64 * 72);
        const __half* cl = ch + 64 * 72;
        float acc[2][4][4] = {};
        #pragma unroll
        for (int ks = 0; ks < 4; ks++) {
            uint32_t Bh[2][4], Bl[2][4];
            #pragma unroll
            for (int nt = 0; nt < 2; nt++) {
                ldsm_x4(Bh[nt], ch + (brow + nt * 16) * 72 + ks * 16 + bcol);
                ldsm_x4(Bl[nt], cl + (brow + nt * 16) * 72 + ks * 16 + bcol);
            }
            #pragma unroll
            for (int nt = 0; nt < 2; nt++)
                #pragma unroll
                for (int m = 0; m < 2; m++) {
                    mma16816(acc[m][nt * 2],     Ah[m][ks], &Bh[nt][0]);
                    mma16816(acc[m][nt * 2],     Ah[m][ks], &Bl[nt][0]);
                    mma16816(acc[m][nt * 2 + 1], Ah[m][ks], &Bh[nt][2]);
                    mma16816(acc[m][nt * 2 + 1], Ah[m][ks], &Bl[nt][2]);
                }
        }
        // store this d-chunk
        #pragma unroll
        for (int m = 0; m < 2; m++)
            #pragma unroll
            for (int n = 0; n < 4; n++) {
                const size_t r = (size_t)(row0 + rg * 32 + m * 16 + gid);
                const int d = c * 64 + ng * 32 + n * 8 + tig * 2;
                float* po = out + r * DIM + d;
                po[0] = acc[m][n][0] * OUT_S;
                po[1] = acc[m][n][1] * OUT_S;
                po[8 * DIM] = acc[m][n][2] * OUT_S;
                po[8 * DIM + 1] = acc[m][n][3] * OUT_S;
            }
        if (c < 15) sts_cv((c + 1) & 1);
        __syncthreads();
        if (c < 14) ldg_cv(c + 2);
    }
}

// ---------------------------------------------------------------------------
extern "C" void kernel_launch(void* const* d_in, const int* in_sizes, int n_in,
                              void* d_out, int out_size)
{
    const float* x    = (const float*)d_in[0];
    const int*   mask = (const int*)d_in[1];
    const float* W_Q  = (const float*)d_in[2];
    const float* b_Q  = (const float*)d_in[3];
    const float* C_K  = (const float*)d_in[4];
    const float* C_V  = (const float*)d_in[5];
    float*       out  = (float*)d_out;

    cudaFuncSetAttribute(fused_mma, cudaFuncAttributeMaxDynamicSharedMemorySize, SMEM_BYTES);
    prep_partial<<<KSPLIT * 16, 256>>>(W_Q, C_K);
    prep_reduce<<<257, 256>>>(b_Q, C_K, C_V);
    fused_mma<<<NCTA, 256, SMEM_BYTES>>>(x, mask, out);
}

// round 9
// speedup vs baseline: 2.8881x; 1.0117x over previous
#include <cuda_runtime.h>
#include <cuda_fp16.h>
#include <cstdint>
#include <cstddef>

#define DIM    1024
#define ALPHA  64
#define NROWS  32768
#define SCALE  0.03125f        // 1/sqrt(1024)
#define TILE_ROWS 128
#define NCTA   (NROWS / TILE_ROWS)

// operand pre-scales (powers of 2, folded out exactly)
#define MT_S   256.0f
#define INV_MT (1.0f / 256.0f)
#define A_S    1024.0f
#define CV_S   64.0f
#define OUT_S  (1.0f / (1024.0f * 64.0f))

// smem layout (bytes), aliased by lifetime:
//   phase1: xs[2][128][72]h @0 (36864), mts[2][64][72]h @36864 (18432)
//   phase2: ls[128][68]f @0 (34816)                 [xs dead, mma(15) synced]
//   A hi:   ahs[128][72]h @55296 (18432)            [alive thru phase3]
//   phase3: cvh[2]/cvl[2] 4x9216 @0                 [ls dead]
#define XS_OFF   0
#define MTS_OFF  36864
#define LS_OFF   0
#define AH_OFF   55296
#define CV_OFF   0
#define BIAS_OFF 73728
#define SMEM_BYTES 73984

#define KSPLIT 32
__device__ float  g_part[KSPLIT * ALPHA * DIM];
__device__ float  g_bias[ALPHA];
__device__ __half g_Mth[ALPHA * DIM];           // Mt[a][d] * 256
__device__ __half g_CVh[DIM * ALPHA];           // C_V[d][a]*64 hi
__device__ __half g_CVl[DIM * ALPHA];           // residual lo

// ---------------- helpers ----------------
__device__ __forceinline__ uint32_t fpack(float a, float b) {
    __half2 h = __floats2half2_rn(a, b);
    return *reinterpret_cast<uint32_t*>(&h);
}
__device__ __forceinline__ void mma16816(float* c, const uint32_t* a, const uint32_t* b) {
    asm volatile("mma.sync.aligned.m16n8k16.row.col.f32.f16.f16.f32 "
        "{%0,%1,%2,%3}, {%4,%5,%6,%7}, {%8,%9}, {%0,%1,%2,%3};"
        : "+f"(c[0]), "+f"(c[1]), "+f"(c[2]), "+f"(c[3])
        : "r"(a[0]), "r"(a[1]), "r"(a[2]), "r"(a[3]), "r"(b[0]), "r"(b[1]));
}
__device__ __forceinline__ void ldsm_x4(uint32_t* r, const __half* p) {
    uint32_t a = (uint32_t)__cvta_generic_to_shared(p);
    asm volatile("ldmatrix.sync.aligned.m8n8.x4.shared.b16 {%0,%1,%2,%3}, [%4];"
        : "=r"(r[0]), "=r"(r[1]), "=r"(r[2]), "=r"(r[3]) : "r"(a));
}

// ---------------- prep: partial GEMM  Mt_part = C_K^T @ W_Q (K-split 32x32) ----------------
__global__ __launch_bounds__(256) void prep_partial(
    const float* __restrict__ W_Q, const float* __restrict__ C_K)
{
    __shared__ float ck_s[32][68];
    __shared__ float wq_s[32][68];
    const int tid = threadIdx.x;
    const int nb = blockIdx.x & 15, kb = blockIdx.x >> 4;
    const int e0 = kb * 32, d0 = nb * 64;
    #pragma unroll
    for (int j = 0; j < 2; j++) {
        const int v = tid + 256 * j;
        const int e = v >> 4, q = v & 15;
        *(float4*)&ck_s[e][q * 4] = *(const float4*)&C_K[(e0 + e) * ALPHA + q * 4];
        *(float4*)&wq_s[e][q * 4] = *(const float4*)&W_Q[(size_t)(e0 + e) * DIM + d0 + q * 4];
    }
    __syncthreads();
    const int tx = tid & 15, ty = tid >> 4;
    float acc[4][4] = {};
    #pragma unroll 8
    for (int e = 0; e < 32; e++) {
        const float4 av = *(const float4*)&ck_s[e][ty * 4];
        const float4 bv = *(const float4*)&wq_s[e][tx * 4];
        const float aa[4] = {av.x, av.y, av.z, av.w};
        const float bb[4] = {bv.x, bv.y, bv.z, bv.w};
        #pragma unroll
        for (int i = 0; i < 4; i++)
            #pragma unroll
            for (int j = 0; j < 4; j++) acc[i][j] += aa[i] * bb[j];
    }
    #pragma unroll
    for (int i = 0; i < 4; i++) {
        float4 w; w.x = acc[i][0]; w.y = acc[i][1]; w.z = acc[i][2]; w.w = acc[i][3];
        *(float4*)&g_part[kb * (ALPHA * DIM) + (ty * 4 + i) * DIM + d0 + tx * 4] = w;
    }
}

// ---------------- prep: reduce + convert ----------------
__global__ __launch_bounds__(256) void prep_reduce(
    const float* __restrict__ b_Q, const float* __restrict__ C_K,
    const float* __restrict__ C_V)
{
    __shared__ float red[256];
    const int tid = threadIdx.x;
    if (blockIdx.x == 256) {                         // bias block
        const int a = tid & 63, ks = tid >> 6;
        float s = 0.f;
        for (int e = ks * 256; e < ks * 256 + 256; e++)
            s += b_Q[e] * C_K[e * ALPHA + a];
        red[tid] = s;
        __syncthreads();
        if (tid < 64)
            g_bias[tid] = (red[tid] + red[tid + 64] + red[tid + 128] + red[tid + 192]) * SCALE;
        return;
    }
    const int o = blockIdx.x * 256 + tid;
    float s = 0.f;
    #pragma unroll
    for (int p = 0; p < KSPLIT; p++) s += g_part[p * (ALPHA * DIM) + o];
    g_Mth[o] = __float2half_rn(s * SCALE * MT_S);
    const float cv = C_V[o] * CV_S;
    const __half ch = __float2half_rn(cv);
    g_CVh[o] = ch;
    g_CVl[o] = __float2half_rn(cv - __half2float(ch));
}

// ---------------- fused: 1 CTA = 128 rows, 256 threads, 2 CTAs/SM ----------------
__global__ __launch_bounds__(256, 2) void fused_mma(
    const float* __restrict__ x, const int* __restrict__ mask,
    float* __restrict__ out)
{
    extern __shared__ __align__(16) char sm[];
    __half* xs  = (__half*)(sm + XS_OFF);            // 2 bufs of 128*72
    __half* mts = (__half*)(sm + MTS_OFF);           // 2 bufs of 64*72
    float*  ls  = (float*)(sm + LS_OFF);
    __half* ahs = (__half*)(sm + AH_OFF);
    __half* cvs = (__half*)(sm + CV_OFF);            // [buf][hi/lo] 4 x 64*72
    float*  bsm = (float*)(sm + BIAS_OFF);

    const int tid  = threadIdx.x;
    const int lane = tid & 31, wid = tid >> 5;
    const int gid  = lane >> 2, tig = lane & 3;
    const int rg   = wid >> 1, ng = wid & 1;
    const int row0 = blockIdx.x * TILE_ROWS;

    if (tid < ALPHA) bsm[tid] = g_bias[tid];

    // ldmatrix per-lane coords
    const int arow = rg * 32 + (lane & 15);          // A-frag rows (+ m*16)
    const int acol = (lane >> 4) * 8;                // A-frag k sub-offset
    const int brow = ng * 32 + (lane & 7) + ((lane >> 4) & 1) * 8;  // B rows (+ nt*16)
    const int bcol = ((lane >> 3) & 1) * 8;          // B k sub-offset

    // loader coords
    const int lrow = tid >> 1, lk0 = (tid & 1) * 32;

    float4 xv[8];
    uint4  mtv[2];

    auto ldg_x = [&](int c) {
        const float* xp = x + (size_t)(row0 + lrow) * DIM + c * 64 + lk0;
        #pragma unroll
        for (int j = 0; j < 8; j++) xv[j] = *(const float4*)(xp + j * 4);
        const char* mb = (const char*)g_Mth;
        #pragma unroll
        for (int jj = 0; jj < 2; jj++) {
            const int j = tid * 2 + jj;
            mtv[jj] = *(const uint4*)(mb + (j >> 3) * 2048 + c * 128 + (j & 7) * 16);
        }
    };
    auto sts_x = [&](int b) {
        uint32_t hp[16];
        #pragma unroll
        for (int j = 0; j < 8; j++) {
            hp[2 * j]     = fpack(xv[j].x, xv[j].y);
            hp[2 * j + 1] = fpack(xv[j].z, xv[j].w);
        }
        uint4* xd = (uint4*)(xs + b * (128 * 72) + lrow * 72 + lk0);
        #pragma unroll
        for (int q = 0; q < 4; q++)
            xd[q] = make_uint4(hp[4 * q], hp[4 * q + 1], hp[4 * q + 2], hp[4 * q + 3]);
        char* md = (char*)(mts + b * (64 * 72));
        #pragma unroll
        for (int jj = 0; jj < 2; jj++) {
            const int j = tid * 2 + jj;
            *(uint4*)(md + (j >> 3) * 144 + (j & 7) * 16) = mtv[jj];
        }
    };

    // ---- phase 1: logits = x @ Mt^T, 16 chunks of k=64, double-buffered ----
    float acc1[2][4][4] = {};
    ldg_x(0);
    sts_x(0);
    __syncthreads();
    ldg_x(1);
    for (int c = 0; c < 16; c++) {
        const __half* xb = xs + (c & 1) * (128 * 72);
        const __half* mbf = mts + (c & 1) * (64 * 72);
        #pragma unroll
        for (int ks = 0; ks < 4; ks++) {
            uint32_t A0[2][4], B0[2][4];
            #pragma unroll
            for (int m = 0; m < 2; m++)
                ldsm_x4(A0[m], xb + (arow + m * 16) * 72 + ks * 16 + acol);
            #pragma unroll
            for (int nt = 0; nt < 2; nt++)
                ldsm_x4(B0[nt], mbf + (brow + nt * 16) * 72 + ks * 16 + bcol);
            #pragma unroll
            for (int nt = 0; nt < 2; nt++)
                #pragma unroll
                for (int m = 0; m < 2; m++) {
                    mma16816(acc1[m][nt * 2],     A0[m], &B0[nt][0]);
                    mma16816(acc1[m][nt * 2 + 1], A0[m], &B0[nt][2]);
                }
        }
        if (c < 15) sts_x((c + 1) & 1);
        __syncthreads();
        if (c < 14) ldg_x(c + 2);
    }

    // stash logits to ls (aliases xs; last sync covers mma(15))
    #pragma unroll
    for (int m = 0; m < 2; m++)
        #pragma unroll
        for (int n = 0; n < 4; n++) {
            const int r = rg * 32 + m * 16 + gid;
            const int cc = ng * 32 + n * 8 + tig * 2;
            float* p = ls + r * 68 + cc;
            p[0] = acc1[m][n][0];
            p[1] = acc1[m][n][1];
            p[8 * 68] = acc1[m][n][2];
            p[8 * 68 + 1] = acc1[m][n][3];
        }
    __syncthreads();

    // ---- phase 2: softmax * mask, emit A fp16 (x A_S) ----
    if (tid < TILE_ROWS) {
        float e[64];
        const float* lp = ls + tid * 68;
        float mx = -1e30f;
        #pragma unroll
        for (int a = 0; a < 64; a++) {
            const float v = lp[a] * INV_MT + bsm[a];
            e[a] = v;
            mx = fmaxf(mx, v);
        }
        float s = 0.f;
        #pragma unroll
        for (int a = 0; a < 64; a++) { e[a] = __expf(e[a] - mx); s += e[a]; }
        const float inv = (mask[row0 + tid] ? A_S : 0.0f) / s;
        __half* ahp = ahs + tid * 72;
        #pragma unroll
        for (int a = 0; a < 64; a++)
            ahp[a] = __float2half_rn(e[a] * inv);
    }
    __syncthreads();

    // ---- phase 3: out = A @ C_V^T, 16 chunks of 64 d, hi+lo, double-buffered ----
    uint32_t Ah[2][4][4];
    #pragma unroll
    for (int m = 0; m < 2; m++)
        #pragma unroll
        for (int ks = 0; ks < 4; ks++)
            ldsm_x4(Ah[m][ks], ahs + (arow + m * 16) * 72 + ks * 16 + acol);

    // C_V loader: 64 d-rows per chunk (hi+lo 32B each per thread)
    const int crow = tid >> 2, cseg = (tid & 3) * 16;
    uint4 cvvh[2], cvvl[2];
    auto ldg_cv = [&](int c) {
        const char* hb = (const char*)g_CVh;
        const char* lb = (const char*)g_CVl;
        const size_t base = (size_t)(c * 64 + crow) * 128 + cseg * 2;
        cvvh[0] = *(const uint4*)(hb + base);
        cvvh[1] = *(const uint4*)(hb + base + 16);
        cvvl[0] = *(const uint4*)(lb + base);
        cvvl[1] = *(const uint4*)(lb + base + 16);
    };
    auto sts_cv = [&](int b) {
        uint4* dh = (uint4*)(cvs + b * 2 * (64 * 72) + crow * 72 + cseg);
        uint4* dl = (uint4*)(cvs + (b * 2 + 1) * (64 * 72) + crow * 72 + cseg);
        dh[0] = cvvh[0]; dh[1] = cvvh[1];
        dl[0] = cvvl[0]; dl[1] = cvvl[1];
    };

    ldg_cv(0);
    sts_cv(0);
    __syncthreads();
    ldg_cv(1);
    for (int c = 0; c < 16; c++) {
        const __half* ch = cvs + (c & 1) * 2 * (64 * 72);
        const __half* cl = ch + 64 * 72;
        float acc[2][4][4] = {};
        #pragma unroll
        for (int ks = 0; ks < 4; ks++) {
            uint32_t Bh[2][4], Bl[2][4];
            #pragma unroll
            for (int nt = 0; nt < 2; nt++) {
                ldsm_x4(Bh[nt], ch + (brow + nt * 16) * 72 + ks * 16 + bcol);
                ldsm_x4(Bl[nt], cl + (brow + nt * 16) * 72 + ks * 16 + bcol);
            }
            #pragma unroll
            for (int nt = 0; nt < 2; nt++)
                #pragma unroll
                for (int m = 0; m < 2; m++) {
                    mma16816(acc[m][nt * 2],     Ah[m][ks], &Bh[nt][0]);
                    mma16816(acc[m][nt * 2],     Ah[m][ks], &Bl[nt][0]);
                    mma16816(acc[m][nt * 2 + 1], Ah[m][ks], &Bh[nt][2]);
                    mma16816(acc[m][nt * 2 + 1], Ah[m][ks], &Bl[nt][2]);
                }
        }
        // store this d-chunk
        #pragma unroll
        for (int m = 0; m < 2; m++)
            #pragma unroll
            for (int n = 0; n < 4; n++) {
                const size_t r = (size_t)(row0 + rg * 32 + m * 16 + gid);
                const int d = c * 64 + ng * 32 + n * 8 + tig * 2;
                float* po = out + r * DIM + d;
                po[0] = acc[m][n][0] * OUT_S;
                po[1] = acc[m][n][1] * OUT_S;
                po[8 * DIM] = acc[m][n][2] * OUT_S;
                po[8 * DIM + 1] = acc[m][n][3] * OUT_S;
            }
        if (c < 15) sts_cv((c + 1) & 1);
        __syncthreads();
        if (c < 14) ldg_cv(c + 2);
    }
}

// ---------------------------------------------------------------------------
extern "C" void kernel_launch(void* const* d_in, const int* in_sizes, int n_in,
                              void* d_out, int out_size)
{
    const float* x    = (const float*)d_in[0];
    const int*   mask = (const int*)d_in[1];
    const float* W_Q  = (const float*)d_in[2];
    const float* b_Q  = (const float*)d_in[3];
    const float* C_K  = (const float*)d_in[4];
    const float* C_V  = (const float*)d_in[5];
    float*       out  = (float*)d_out;

    cudaFuncSetAttribute(fused_mma, cudaFuncAttributeMaxDynamicSharedMemorySize, SMEM_BYTES);
    prep_partial<<<KSPLIT * 16, 256>>>(W_Q, C_K);
    prep_reduce<<<257, 256>>>(b_Q, C_K, C_V);
    fused_mma<<<NCTA, 256, SMEM_BYTES>>>(x, mask, out);
}

// round 11
// speedup vs baseline: 3.1126x; 1.0777x over previous
#include <cuda_runtime.h>
#include <cuda_fp16.h>
#include <cstdint>
#include <cstddef>

#define DIM    1024
#define ALPHA  64
#define NROWS  32768
#define SCALE  0.03125f        // 1/sqrt(1024)
#define TILE_ROWS 128
#define NCTA   (NROWS / TILE_ROWS)

// operand pre-scales (powers of 2, folded out exactly)
#define MT_S   256.0f
#define INV_MT (1.0f / 256.0f)
#define A_S    1024.0f
#define CV_S   64.0f
#define OUT_S  (1.0f / (1024.0f * 64.0f))

// smem layout (bytes), aliased by lifetime:
//   phase1: xs[2][128][72]h @0 (36864), mts[2][64][72]h @36864 (18432)
//   phase2: ls[128][68]f @0 (34816)                 [xs dead, mma(15) synced]
//   A hi:   ahs[128][72]h @55296 (18432)            [alive thru phase3]
//   phase3: cvh[2] 2x9216 @0                        [ls dead]
#define XS_OFF   0
#define MTS_OFF  36864
#define LS_OFF   0
#define AH_OFF   55296
#define CV_OFF   0
#define BIAS_OFF 73728
#define SMEM_BYTES 73984

#define KSPLIT 32
__device__ float  g_part[KSPLIT * ALPHA * DIM];
__device__ float  g_bias[ALPHA];
__device__ __half g_Mth[ALPHA * DIM];           // Mt[a][d] * 256
__device__ __half g_CVh[DIM * ALPHA];           // C_V[d][a]*64

// ---------------- helpers ----------------
__device__ __forceinline__ uint32_t fpack(float a, float b) {
    __half2 h = __floats2half2_rn(a, b);
    return *reinterpret_cast<uint32_t*>(&h);
}
__device__ __forceinline__ void mma16816(float* c, const uint32_t* a, const uint32_t* b) {
    asm volatile("mma.sync.aligned.m16n8k16.row.col.f32.f16.f16.f32 "
        "{%0,%1,%2,%3}, {%4,%5,%6,%7}, {%8,%9}, {%0,%1,%2,%3};"
        : "+f"(c[0]), "+f"(c[1]), "+f"(c[2]), "+f"(c[3])
        : "r"(a[0]), "r"(a[1]), "r"(a[2]), "r"(a[3]), "r"(b[0]), "r"(b[1]));
}
__device__ __forceinline__ void ldsm_x4(uint32_t* r, const __half* p) {
    uint32_t a = (uint32_t)__cvta_generic_to_shared(p);
    asm volatile("ldmatrix.sync.aligned.m8n8.x4.shared.b16 {%0,%1,%2,%3}, [%4];"
        : "=r"(r[0]), "=r"(r[1]), "=r"(r[2]), "=r"(r[3]) : "r"(a));
}

// ---------------- prep: partial GEMM  Mt_part = C_K^T @ W_Q (K-split 32x32) ----------------
__global__ __launch_bounds__(256) void prep_partial(
    const float* __restrict__ W_Q, const float* __restrict__ C_K)
{
    __shared__ float ck_s[32][68];
    __shared__ float wq_s[32][68];
    const int tid = threadIdx.x;
    const int nb = blockIdx.x & 15, kb = blockIdx.x >> 4;
    const int e0 = kb * 32, d0 = nb * 64;
    #pragma unroll
    for (int j = 0; j < 2; j++) {
        const int v = tid + 256 * j;
        const int e = v >> 4, q = v & 15;
        *(float4*)&ck_s[e][q * 4] = *(const float4*)&C_K[(e0 + e) * ALPHA + q * 4];
        *(float4*)&wq_s[e][q * 4] = *(const float4*)&W_Q[(size_t)(e0 + e) * DIM + d0 + q * 4];
    }
    __syncthreads();
    const int tx = tid & 15, ty = tid >> 4;
    float acc[4][4] = {};
    #pragma unroll 8
    for (int e = 0; e < 32; e++) {
        const float4 av = *(const float4*)&ck_s[e][ty * 4];
        const float4 bv = *(const float4*)&wq_s[e][tx * 4];
        const float aa[4] = {av.x, av.y, av.z, av.w};
        const float bb[4] = {bv.x, bv.y, bv.z, bv.w};
        #pragma unroll
        for (int i = 0; i < 4; i++)
            #pragma unroll
            for (int j = 0; j < 4; j++) acc[i][j] += aa[i] * bb[j];
    }
    #pragma unroll
    for (int i = 0; i < 4; i++) {
        float4 w; w.x = acc[i][0]; w.y = acc[i][1]; w.z = acc[i][2]; w.w = acc[i][3];
        *(float4*)&g_part[kb * (ALPHA * DIM) + (ty * 4 + i) * DIM + d0 + tx * 4] = w;
    }
}

// ---------------- prep: reduce + convert ----------------
__global__ __launch_bounds__(256) void prep_reduce(
    const float* __restrict__ b_Q, const float* __restrict__ C_K,
    const float* __restrict__ C_V)
{
    __shared__ float red[256];
    const int tid = threadIdx.x;
    if (blockIdx.x == 256) {                         // bias block
        const int a = tid & 63, ks = tid >> 6;
        float s = 0.f;
        for (int e = ks * 256; e < ks * 256 + 256; e++)
            s += b_Q[e] * C_K[e * ALPHA + a];
        red[tid] = s;
        __syncthreads();
        if (tid < 64)
            g_bias[tid] = (red[tid] + red[tid + 64] + red[tid + 128] + red[tid + 192]) * SCALE;
        return;
    }
    const int o = blockIdx.x * 256 + tid;
    float s = 0.f;
    #pragma unroll
    for (int p = 0; p < KSPLIT; p++) s += g_part[p * (ALPHA * DIM) + o];
    g_Mth[o] = __float2half_rn(s * SCALE * MT_S);
    g_CVh[o] = __float2half_rn(C_V[o] * CV_S);
}

// ---------------- fused: 1 CTA = 128 rows, 256 threads, 2 CTAs/SM ----------------
__global__ __launch_bounds__(256, 2) void fused_mma(
    const float* __restrict__ x, const int* __restrict__ mask,
    float* __restrict__ out)
{
    extern __shared__ __align__(16) char sm[];
    __half* xs  = (__half*)(sm + XS_OFF);            // 2 bufs of 128*72
    __half* mts = (__half*)(sm + MTS_OFF);           // 2 bufs of 64*72
    float*  ls  = (float*)(sm + LS_OFF);
    __half* ahs = (__half*)(sm + AH_OFF);
    __half* cvs = (__half*)(sm + CV_OFF);            // 2 bufs of 64*72
    float*  bsm = (float*)(sm + BIAS_OFF);

    const int tid  = threadIdx.x;
    const int lane = tid & 31, wid = tid >> 5;
    const int gid  = lane >> 2, tig = lane & 3;
    const int rg   = wid >> 1, ng = wid & 1;
    const int row0 = blockIdx.x * TILE_ROWS;

    if (tid < ALPHA) bsm[tid] = g_bias[tid];

    // ldmatrix per-lane coords
    const int arow = rg * 32 + (lane & 15);
    const int acol = (lane >> 4) * 8;
    const int brow = ng * 32 + (lane & 7) + ((lane >> 4) & 1) * 8;
    const int bcol = ((lane >> 3) & 1) * 8;

    // loader coords
    const int lrow = tid >> 1, lk0 = (tid & 1) * 32;

    float4 xv[8];
    uint4  mtv[2];

    auto ldg_x = [&](int c) {
        const float* xp = x + (size_t)(row0 + lrow) * DIM + c * 64 + lk0;
        #pragma unroll
        for (int j = 0; j < 8; j++) xv[j] = *(const float4*)(xp + j * 4);
        const char* mb = (const char*)g_Mth;
        #pragma unroll
        for (int jj = 0; jj < 2; jj++) {
            const int j = tid * 2 + jj;
            mtv[jj] = *(const uint4*)(mb + (j >> 3) * 2048 + c * 128 + (j & 7) * 16);
        }
    };
    auto sts_x = [&](int b) {
        uint32_t hp[16];
        #pragma unroll
        for (int j = 0; j < 8; j++) {
            hp[2 * j]     = fpack(xv[j].x, xv[j].y);
            hp[2 * j + 1] = fpack(xv[j].z, xv[j].w);
        }
        uint4* xd = (uint4*)(xs + b * (128 * 72) + lrow * 72 + lk0);
        #pragma unroll
        for (int q = 0; q < 4; q++)
            xd[q] = make_uint4(hp[4 * q], hp[4 * q + 1], hp[4 * q + 2], hp[4 * q + 3]);
        char* md = (char*)(mts + b * (64 * 72));
        #pragma unroll
        for (int jj = 0; jj < 2; jj++) {
            const int j = tid * 2 + jj;
            *(uint4*)(md + (j >> 3) * 144 + (j & 7) * 16) = mtv[jj];
        }
    };

    // ---- phase 1: logits = x @ Mt^T, 16 chunks of k=64, double-buffered ----
    float acc1[2][4][4] = {};
    ldg_x(0);
    sts_x(0);
    __syncthreads();
    ldg_x(1);
    for (int c = 0; c < 16; c++) {
        const __half* xb  = xs + (c & 1) * (128 * 72);
        const __half* mbf = mts + (c & 1) * (64 * 72);
        #pragma unroll
        for (int ks = 0; ks < 4; ks++) {
            uint32_t A0[2][4], B0[2][4];
            #pragma unroll
            for (int m = 0; m < 2; m++)
                ldsm_x4(A0[m], xb + (arow + m * 16) * 72 + ks * 16 + acol);
            #pragma unroll
            for (int nt = 0; nt < 2; nt++)
                ldsm_x4(B0[nt], mbf + (brow + nt * 16) * 72 + ks * 16 + bcol);
            #pragma unroll
            for (int nt = 0; nt < 2; nt++)
                #pragma unroll
                for (int m = 0; m < 2; m++) {
                    mma16816(acc1[m][nt * 2],     A0[m], &B0[nt][0]);
                    mma16816(acc1[m][nt * 2 + 1], A0[m], &B0[nt][2]);
                }
        }
        if (c < 15) sts_x((c + 1) & 1);
        __syncthreads();
        if (c < 14) ldg_x(c + 2);
    }

    // stash logits to ls (aliases xs; last sync covers mma(15))
    #pragma unroll
    for (int m = 0; m < 2; m++)
        #pragma unroll
        for (int n = 0; n < 4; n++) {
            const int r = rg * 32 + m * 16 + gid;
            const int cc = ng * 32 + n * 8 + tig * 2;
            float* p = ls + r * 68 + cc;
            p[0] = acc1[m][n][0];
            p[1] = acc1[m][n][1];
            p[8 * 68] = acc1[m][n][2];
            p[8 * 68 + 1] = acc1[m][n][3];
        }
    __syncthreads();

    // C_V loader (hoisted chunk 0 — hide LDG behind softmax)
    const int crow = tid >> 2, cseg = (tid & 3) * 16;
    uint4 cvvh[2];
    auto ldg_cv = [&](int c) {
        const char* hb = (const char*)g_CVh;
        const size_t base = (size_t)(c * 64 + crow) * 128 + cseg * 2;
        cvvh[0] = *(const uint4*)(hb + base);
        cvvh[1] = *(const uint4*)(hb + base + 16);
    };
    auto sts_cv = [&](int b) {
        uint4* dh = (uint4*)(cvs + b * (64 * 72) + crow * 72 + cseg);
        dh[0] = cvvh[0]; dh[1] = cvvh[1];
    };
    ldg_cv(0);

    // ---- phase 2: softmax * mask, emit A fp16 (x A_S) ----
    if (tid < TILE_ROWS) {
        float e[64];
        const float* lp = ls + tid * 68;
        float mx = -1e30f;
        #pragma unroll
        for (int a = 0; a < 64; a++) {
            const float v = lp[a] * INV_MT + bsm[a];
            e[a] = v;
            mx = fmaxf(mx, v);
        }
        float s = 0.f;
        #pragma unroll
        for (int a = 0; a < 64; a++) { e[a] = __expf(e[a] - mx); s += e[a]; }
        const float inv = (mask[row0 + tid] ? A_S : 0.0f) / s;
        __half* ahp = ahs + tid * 72;
        #pragma unroll
        for (int a = 0; a < 64; a++)
            ahp[a] = __float2half_rn(e[a] * inv);
    }
    __syncthreads();        // ls dead; cvs region free; ahs ready

    // ---- phase 3: out = A @ C_V^T, 16 chunks of 64 d, hi-pass, double-buffered ----
    sts_cv(0);
    uint32_t Ah[2][4][4];
    #pragma unroll
    for (int m = 0; m < 2; m++)
        #pragma unroll
        for (int ks = 0; ks < 4; ks++)
            ldsm_x4(Ah[m][ks], ahs + (arow + m * 16) * 72 + ks * 16 + acol);
    __syncthreads();
    ldg_cv(1);
    for (int c = 0; c < 16; c++) {
        const __half* ch = cvs + (c & 1) * (64 * 72);
        float acc[2][4][4] = {};
        #pragma unroll
        for (int ks = 0; ks < 4; ks++) {
            uint32_t Bh[2][4];
            #pragma unroll
            for (int nt = 0; nt < 2; nt++)
                ldsm_x4(Bh[nt], ch + (brow + nt * 16) * 72 + ks * 16 + bcol);
            #pragma unroll
            for (int nt = 0; nt < 2; nt++)
                #pragma unroll
                for (int m = 0; m < 2; m++) {
                    mma16816(acc[m][nt * 2],     Ah[m][ks], &Bh[nt][0]);
                    mma16816(acc[m][nt * 2 + 1], Ah[m][ks], &Bh[nt][2]);
                }
        }
        // store this d-chunk
        #pragma unroll
        for (int m = 0; m < 2; m++)
            #pragma unroll
            for (int n = 0; n < 4; n++) {
                const size_t r = (size_t)(row0 + rg * 32 + m * 16 + gid);
                const int d = c * 64 + ng * 32 + n * 8 + tig * 2;
                float* po = out + r * DIM + d;
                po[0] = acc[m][n][0] * OUT_S;
                po[1] = acc[m][n][1] * OUT_S;
                po[8 * DIM] = acc[m][n][2] * OUT_S;
                po[8 * DIM + 1] = acc[m][n][3] * OUT_S;
            }
        if (c < 15) sts_cv((c + 1) & 1);
        __syncthreads();
        if (c < 14) ldg_cv(c + 2);
    }
}

// ---------------------------------------------------------------------------
extern "C" void kernel_launch(void* const* d_in, const int* in_sizes, int n_in,
                              void* d_out, int out_size)
{
    const float* x    = (const float*)d_in[0];
    const int*   mask = (const int*)d_in[1];
    const float* W_Q  = (const float*)d_in[2];
    const float* b_Q  = (const float*)d_in[3];
    const float* C_K  = (const float*)d_in[4];
    const float* C_V  = (const float*)d_in[5];
    float*       out  = (float*)d_out;

    cudaFuncSetAttribute(fused_mma, cudaFuncAttributeMaxDynamicSharedMemorySize, SMEM_BYTES);
    prep_partial<<<KSPLIT * 16, 256>>>(W_Q, C_K);
    prep_reduce<<<257, 256>>>(b_Q, C_K, C_V);
    fused_mma<<<NCTA, 256, SMEM_BYTES>>>(x, mask, out);
}